// round 4
// baseline (speedup 1.0000x reference)
#include <cuda_runtime.h>

// Problem constants
#define Bg    16
#define NPGc  2048
#define NNc   32768      // Bg * NPGc
#define CINc  64
#define HIDc  128
#define KCc   32
#define EEc   524288

// ---------------- device scratch (no allocations allowed) ----------------
// Vector-accessed arrays are float4 for guaranteed 16B alignment.
__device__ float4 g_hlin4[NNc*HIDc/4];    // xn @ W1 (pre-aggregation)
__device__ float4 g_hagg4[NNc*HIDc/4];    // scatter accumulator
__device__ float4 g_h4[NNc*HIDc/4];       // relu'd GCN output
__device__ float4 g_s4[NNc*KCc/4];        // softmax assignments
#define g_hlin ((float*)g_hlin4)
#define g_hagg ((float*)g_hagg4)
#define g_h    ((float*)g_h4)
#define g_s    ((float*)g_s4)

__device__ int   g_src[EEc];
__device__ int   g_dst[EEc];
__device__ int   g_is64;

__device__ float g_shift[Bg*CINc];
__device__ float g_scale[Bg*CINc];
__device__ float g_dis[NNc];              // rsqrt(in_deg + 1)
__device__ float g_degdst[NNc];
__device__ float g_degsrc[NNc];           // DMoN degrees (out-degree)
__device__ float g_ecount[Bg];
__device__ float g_trace[Bg];             // sum_e dot(s_src, s_dst)
__device__ float g_sx[Bg*KCc*HIDc];       // S^T X per graph
__device__ float g_ss[Bg*KCc*KCc];        // S^T S per graph
__device__ float g_ca[Bg*KCc];            // S^T degrees
__device__ float g_cs[Bg*KCc];            // cluster sizes

// ---------------- K_detect: is the edge buffer int64 or int32? ----------------
// Node ids < 2^15, so if int64, every odd 32-bit word (hi half) is 0.
// If int32, odd words are src node ids (~random in [0,32768)); all-zero over
// 256 samples is impossible in practice. Deterministic given the input.
__global__ __launch_bounds__(256) void k_detect(const int* __restrict__ ebuf) {
    __shared__ int nz;
    if (threadIdx.x == 0) nz = 0;
    __syncthreads();
    if (ebuf[threadIdx.x * 2 + 1] != 0) atomicOr(&nz, 1);
    __syncthreads();
    if (threadIdx.x == 0) g_is64 = (nz == 0) ? 1 : 0;
}

// ---------------- K_convert: canonical int32 src/dst ----------------
__global__ __launch_bounds__(256) void k_convert(const void* __restrict__ ebuf) {
    int e = blockIdx.x * 256 + threadIdx.x;
    if (e >= EEc) return;
    if (g_is64) {
        const long long* p = (const long long*)ebuf;
        g_src[e] = (int)p[e] & (NNc - 1);
        g_dst[e] = (int)p[EEc + e] & (NNc - 1);
    } else {
        const int* p = (const int*)ebuf;
        g_src[e] = p[e] & (NNc - 1);
        g_dst[e] = p[EEc + e] & (NNc - 1);
    }
}

// ---------------- K0: zero accumulators ----------------
__global__ __launch_bounds__(256) void k_zero() {
    int i0 = blockIdx.x * blockDim.x + threadIdx.x;
    int stride = gridDim.x * blockDim.x;
    float4 z4 = make_float4(0.f, 0.f, 0.f, 0.f);
    for (int i = i0; i < NNc*HIDc/4; i += stride) g_hagg4[i] = z4;
    for (int i = i0; i < NNc; i += stride) { g_degdst[i] = 0.f; g_degsrc[i] = 0.f; }
    for (int i = i0; i < Bg*KCc*HIDc; i += stride) g_sx[i] = 0.f;
    for (int i = i0; i < Bg*KCc*KCc; i += stride) g_ss[i] = 0.f;
    for (int i = i0; i < Bg*KCc; i += stride) { g_ca[i] = 0.f; g_cs[i] = 0.f; }
    if (i0 < Bg) { g_ecount[i0] = 0.f; g_trace[i0] = 0.f; }
}

// ---------------- K1: GraphNorm statistics ----------------
__global__ __launch_bounds__(256) void k_gn_stats(const float* __restrict__ x,
                                                  const float* __restrict__ gnw,
                                                  const float* __restrict__ gms) {
    __shared__ float ssum[256], ssq[256];
    int b = blockIdx.x;
    int c = threadIdx.x & 63, r0 = threadIdx.x >> 6;
    const float* xb = x + (size_t)b * NPGc * CINc;
    float s = 0.f, q = 0.f;
    for (int r = r0; r < NPGc; r += 4) {
        float v = xb[r * CINc + c];
        s += v; q += v * v;
    }
    ssum[threadIdx.x] = s; ssq[threadIdx.x] = q;
    __syncthreads();
    if (threadIdx.x < 64) {
        s = ssum[c] + ssum[c+64] + ssum[c+128] + ssum[c+192];
        q = ssq[c] + ssq[c+64] + ssq[c+128] + ssq[c+192];
        float mean = s * (1.f / NPGc);
        float ms = gms[c];
        // var = E[(x - ms*mean)^2] = E[x^2] - 2*ms*mean*E[x] + (ms*mean)^2
        float var = q * (1.f / NPGc) - 2.f * ms * mean * mean + ms * ms * mean * mean;
        float istd = rsqrtf(var + 1e-5f);
        g_shift[b*CINc + c] = mean * ms;
        g_scale[b*CINc + c] = gnw[c] * istd;
    }
}

// ---------------- K2: GraphNorm apply + GEMM xn @ W1 -> g_hlin ----------------
__global__ __launch_bounds__(256) void k_gemm1(const float* __restrict__ x,
                                               const float* __restrict__ gnb,
                                               const float* __restrict__ W1) {
    __shared__ float Ws[CINc][HIDc];     // 32 KB
    __shared__ float Xs[32][CINc + 1];   // 8.1 KB
    int n0 = blockIdx.x * 32;
    int b = n0 / NPGc;
    for (int i = threadIdx.x; i < 32 * CINc; i += 256) {
        int r = i >> 6, c = i & 63;
        float v = x[(size_t)(n0 + r) * CINc + c];
        Xs[r][c] = (v - g_shift[b*CINc + c]) * g_scale[b*CINc + c] + gnb[c];
    }
    for (int i = threadIdx.x; i < CINc * HIDc; i += 256)
        Ws[i >> 7][i & 127] = W1[i];
    __syncthreads();

    int q = threadIdx.x & 7;
    int jg = threadIdx.x >> 3;
    float acc[4][4];
#pragma unroll
    for (int i = 0; i < 4; i++)
#pragma unroll
        for (int j = 0; j < 4; j++) acc[i][j] = 0.f;

    for (int k = 0; k < CINc; k++) {
        float a0 = Xs[q*4+0][k], a1 = Xs[q*4+1][k], a2 = Xs[q*4+2][k], a3 = Xs[q*4+3][k];
        float w0 = Ws[k][jg*4+0], w1 = Ws[k][jg*4+1], w2 = Ws[k][jg*4+2], w3 = Ws[k][jg*4+3];
        acc[0][0] += a0*w0; acc[0][1] += a0*w1; acc[0][2] += a0*w2; acc[0][3] += a0*w3;
        acc[1][0] += a1*w0; acc[1][1] += a1*w1; acc[1][2] += a1*w2; acc[1][3] += a1*w3;
        acc[2][0] += a2*w0; acc[2][1] += a2*w1; acc[2][2] += a2*w2; acc[2][3] += a2*w3;
        acc[3][0] += a3*w0; acc[3][1] += a3*w1; acc[3][2] += a3*w2; acc[3][3] += a3*w3;
    }
#pragma unroll
    for (int i = 0; i < 4; i++)
#pragma unroll
        for (int j = 0; j < 4; j++)
            g_hlin[(size_t)(n0 + q*4 + i) * HIDc + jg*4 + j] = acc[i][j];
}

// ---------------- K3: degree histograms + per-graph edge counts ----------------
__global__ __launch_bounds__(256) void k_deg() {
    __shared__ float ec[Bg];
    if (threadIdx.x < Bg) ec[threadIdx.x] = 0.f;
    __syncthreads();
    int e = blockIdx.x * 256 + threadIdx.x;
    if (e < EEc) {
        int s = g_src[e];
        int d = g_dst[e];
        atomicAdd(&g_degdst[d], 1.f);
        atomicAdd(&g_degsrc[s], 1.f);
        atomicAdd(&ec[s >> 11], 1.f);   // s / NPGc
    }
    __syncthreads();
    if (threadIdx.x < Bg) atomicAdd(&g_ecount[threadIdx.x], ec[threadIdx.x]);
}

// ---------------- K4: dis = rsqrt(deg_in + 1) ----------------
__global__ __launch_bounds__(256) void k_dis() {
    int i = blockIdx.x * 256 + threadIdx.x;
    if (i < NNc) g_dis[i] = rsqrtf(g_degdst[i] + 1.f);
}

// ---------------- K5: edge scatter (the hot loop) ----------------
// One warp per edge. lane l handles 4 contiguous floats, vector red to L2.
__global__ __launch_bounds__(256) void k_scatter() {
    int w = (blockIdx.x * 256 + threadIdx.x) >> 5;
    int lane = threadIdx.x & 31;
    if (w >= EEc) return;
    int s = g_src[w];
    int d = g_dst[w];
    float c = g_dis[s] * g_dis[d];
    float4 v = g_hlin4[(size_t)s * (HIDc/4) + lane];
    float4* out = &g_hagg4[(size_t)d * (HIDc/4) + lane];
    asm volatile("red.global.add.v4.f32 [%0], {%1,%2,%3,%4};"
                 :: "l"(out), "f"(v.x*c), "f"(v.y*c), "f"(v.z*c), "f"(v.w*c)
                 : "memory");
}

// ---------------- K6: finalize h (self-loop + bias + relu) and compute s ----------------
__global__ __launch_bounds__(256) void k_finalize_s(const float* __restrict__ b1,
                                                    const float* __restrict__ Wp,
                                                    const float* __restrict__ bp,
                                                    float* __restrict__ out_s) {
    __shared__ float Wps[HIDc * KCc];  // 16 KB
    __shared__ float hs[8][HIDc];      // 4 KB
    for (int i = threadIdx.x; i < HIDc * KCc; i += 256) Wps[i] = Wp[i];
    __syncthreads();
    int warp = threadIdx.x >> 5, lane = threadIdx.x & 31;
    int n = blockIdx.x * 8 + warp;
    float dis = g_dis[n];
    float dis2 = dis * dis;
#pragma unroll
    for (int i = 0; i < 4; i++) {
        int j = lane + i * 32;
        float v = g_hagg[(size_t)n*HIDc + j] + dis2 * g_hlin[(size_t)n*HIDc + j] + b1[j];
        v = fmaxf(v, 0.f);
        hs[warp][j] = v;
        g_h[(size_t)n*HIDc + j] = v;
    }
    __syncwarp();
    float acc = bp[lane];
#pragma unroll 8
    for (int j = 0; j < HIDc; j++)
        acc += hs[warp][j] * Wps[j * KCc + lane];
    float m = acc;
#pragma unroll
    for (int o = 16; o; o >>= 1) m = fmaxf(m, __shfl_xor_sync(0xffffffffu, m, o));
    float e = expf(acc - m);
    float sum = e;
#pragma unroll
    for (int o = 16; o; o >>= 1) sum += __shfl_xor_sync(0xffffffffu, sum, o);
    float sv = e / sum;
    g_s[n*KCc + lane] = sv;
    out_s[n*KCc + lane] = sv;
}

// ---------------- K7: spectral trace = sum_e dot(s_src, s_dst) per graph ----------------
__global__ __launch_bounds__(256) void k_trace() {
    __shared__ float sacc[Bg];
    if (threadIdx.x < Bg) sacc[threadIdx.x] = 0.f;
    __syncthreads();
    int wg = (blockIdx.x * 256 + threadIdx.x) >> 5;  // global warp id, 16 edges each
    int lane = threadIdx.x & 31;
    for (int t = 0; t < 16; t++) {
        int e = wg * 16 + t;
        int sn = g_src[e];
        int dn = g_dst[e];
        float p = g_s[sn*KCc + lane] * g_s[dn*KCc + lane];
#pragma unroll
        for (int o = 16; o; o >>= 1) p += __shfl_xor_sync(0xffffffffu, p, o);
        if (lane == 0) atomicAdd(&sacc[sn >> 11], p);
    }
    __syncthreads();
    if (threadIdx.x < Bg) atomicAdd(&g_trace[threadIdx.x], sacc[threadIdx.x]);
}

// ---------------- K8: node-level reductions per graph ----------------
__global__ __launch_bounds__(256) void k_nodered() {
    __shared__ float sS[16][KCc];
    __shared__ float sH[16][HIDc];
    __shared__ float sD[16];
    int b = blockIdx.x;
    int n0 = b * NPGc + blockIdx.y * 128;
    int k = threadIdx.x >> 3;
    int j8 = threadIdx.x & 7;
    float accx[16];
#pragma unroll
    for (int i = 0; i < 16; i++) accx[i] = 0.f;
    float accss[4] = {0.f, 0.f, 0.f, 0.f};
    float accca = 0.f, acccs = 0.f;

    for (int tile = 0; tile < 8; tile++) {
        int base = n0 + tile * 16;
        __syncthreads();
        for (int i = threadIdx.x; i < 16 * KCc; i += 256)
            sS[i >> 5][i & 31] = g_s[(size_t)(base + (i >> 5)) * KCc + (i & 31)];
        for (int i = threadIdx.x; i < 16 * HIDc; i += 256)
            sH[i >> 7][i & 127] = g_h[(size_t)(base + (i >> 7)) * HIDc + (i & 127)];
        if (threadIdx.x < 16) sD[threadIdx.x] = g_degsrc[base + threadIdx.x];
        __syncthreads();
#pragma unroll 4
        for (int nn = 0; nn < 16; nn++) {
            float sk = sS[nn][k];
#pragma unroll
            for (int jj = 0; jj < 16; jj++)
                accx[jj] += sk * sH[nn][j8 + jj * 8];
#pragma unroll
            for (int i = 0; i < 4; i++) {
                int idx = threadIdx.x * 4 + i;
                accss[i] += sS[nn][idx >> 5] * sS[nn][idx & 31];
            }
            if (threadIdx.x < 32) {
                float sv = sS[nn][threadIdx.x];
                accca += sv * sD[nn];
                acccs += sv;
            }
        }
    }
#pragma unroll
    for (int jj = 0; jj < 16; jj++)
        atomicAdd(&g_sx[b*KCc*HIDc + k*HIDc + j8 + jj*8], accx[jj]);
#pragma unroll
    for (int i = 0; i < 4; i++)
        atomicAdd(&g_ss[b*KCc*KCc + threadIdx.x*4 + i], accss[i]);
    if (threadIdx.x < 32) {
        atomicAdd(&g_ca[b*KCc + threadIdx.x], accca);
        atomicAdd(&g_cs[b*KCc + threadIdx.x], acccs);
    }
}

// ---------------- K9: losses ----------------
__global__ __launch_bounds__(512) void k_losses(float* __restrict__ out_loss) {
    __shared__ float bl[Bg];
    int w = threadIdx.x >> 5, lane = threadIdx.x & 31;
    if (w < Bg) {
        int b = w;
        float m = g_ecount[b] * 0.5f;
        float q = 0.f;
        for (int i = 0; i < 32; i++) {
            float v = g_ss[b*1024 + i*32 + lane];
            q += v * v;
        }
#pragma unroll
        for (int o = 16; o; o >>= 1) q += __shfl_xor_sync(0xffffffffu, q, o);
        float nrm = sqrtf(q);
        float inv_sk = rsqrtf((float)KCc);
        float oo = 0.f;
        for (int i = 0; i < 32; i++) {
            float v = g_ss[b*1024 + i*32 + lane] / nrm - ((i == lane) ? inv_sk : 0.f);
            oo += v * v;
        }
#pragma unroll
        for (int o = 16; o; o >>= 1) oo += __shfl_xor_sync(0xffffffffu, oo, o);
        float cav = g_ca[b*KCc + lane];
        float ca2 = cav * cav;
#pragma unroll
        for (int o = 16; o; o >>= 1) ca2 += __shfl_xor_sync(0xffffffffu, ca2, o);
        float csv = g_cs[b*KCc + lane];
        float cs2 = csv * csv;
#pragma unroll
        for (int o = 16; o; o >>= 1) cs2 += __shfl_xor_sync(0xffffffffu, cs2, o);
        if (lane == 0) {
            float spec = -(g_trace[b] - ca2 / (2.f * m)) / (2.f * m);
            float ortho = sqrtf(oo);
            float clus = sqrtf(cs2) / (float)NPGc * sqrtf((float)KCc) - 1.f;
            bl[b] = spec + ortho + clus;
        }
    }
    __syncthreads();
    if (threadIdx.x == 0) {
        float t = 0.f;
        for (int i = 0; i < Bg; i++) t += bl[i];
        out_loss[0] = t / (float)Bg;
    }
}

// ---------------- K10: selu + log_softmax of out_x ----------------
__global__ __launch_bounds__(128) void k_outx(float* __restrict__ out) {
    __shared__ float redm[4], reds[4];
    int row = blockIdx.x;
    int t = threadIdx.x;
    int warp = t >> 5, lane = t & 31;
    float v = g_sx[row * HIDc + t];
    const float sc = 1.0507009873554805f, al = 1.6732632423543772f;
    v = (v > 0.f) ? sc * v : sc * al * (expf(v) - 1.f);
    float mx = v;
#pragma unroll
    for (int o = 16; o; o >>= 1) mx = fmaxf(mx, __shfl_xor_sync(0xffffffffu, mx, o));
    if (lane == 0) redm[warp] = mx;
    __syncthreads();
    mx = fmaxf(fmaxf(redm[0], redm[1]), fmaxf(redm[2], redm[3]));
    float e = expf(v - mx);
    float sum = e;
#pragma unroll
    for (int o = 16; o; o >>= 1) sum += __shfl_xor_sync(0xffffffffu, sum, o);
    if (lane == 0) reds[warp] = sum;
    __syncthreads();
    sum = reds[0] + reds[1] + reds[2] + reds[3];
    out[row * HIDc + t] = v - mx - logf(sum);
}

// ---------------- launch ----------------
extern "C" void kernel_launch(void* const* d_in, const int* in_sizes, int n_in,
                              void* d_out, int out_size) {
    // Size-based mapping for uniquely-sized tensors; positional fallback.
    int i_x = 0, i_W1 = 4, i_b1 = 5, i_Wp = 6, i_bp = 7, i_ei = 8;
    for (int i = 0; i < n_in; i++) {
        int sz = in_sizes[i];
        if (sz == NNc * CINc)   i_x  = i;   // 2097152
        else if (sz == CINc * HIDc) i_W1 = i;   // 8192
        else if (sz == HIDc)        i_b1 = i;   // 128
        else if (sz == HIDc * KCc)  i_Wp = i;   // 4096
        else if (sz == KCc)         i_bp = i;   // 32
        else if (sz == 2 * EEc)     i_ei = i;   // 1048576
    }
    const float* x   = (const float*)d_in[i_x];
    const float* gnw = (const float*)d_in[1];
    const float* gnb = (const float*)d_in[2];
    const float* gms = (const float*)d_in[3];
    const float* W1  = (const float*)d_in[i_W1];
    const float* b1  = (const float*)d_in[i_b1];
    const float* Wp  = (const float*)d_in[i_Wp];
    const float* bp  = (const float*)d_in[i_bp];
    const void*  ei  = d_in[i_ei];

    float* out = (float*)d_out;
    float* out_loss = out + Bg*KCc*HIDc;          // 65536
    float* out_s    = out + Bg*KCc*HIDc + 1;      // 65537

    k_detect<<<1, 256>>>((const int*)ei);
    k_convert<<<EEc/256, 256>>>(ei);
    k_zero<<<4096, 256>>>();
    k_gn_stats<<<Bg, 256>>>(x, gnw, gms);
    k_gemm1<<<NNc/32, 256>>>(x, gnb, W1);
    k_deg<<<EEc/256, 256>>>();
    k_dis<<<NNc/256, 256>>>();
    k_scatter<<<EEc*32/256, 256>>>();
    k_finalize_s<<<NNc/8, 256>>>(b1, Wp, bp, out_s);
    k_trace<<<EEc/16/8, 256>>>();
    k_nodered<<<dim3(Bg, 16), 256>>>();
    k_losses<<<1, 512>>>(out_loss);
    k_outx<<<Bg*KCc, 128>>>(out);
}

// round 5
// speedup vs baseline: 1.1241x; 1.1241x over previous
#include <cuda_runtime.h>

// Problem constants
#define Bg    16
#define NPGc  2048
#define NNc   32768      // Bg * NPGc
#define CINc  64
#define HIDc  128
#define KCc   32
#define EEc   524288

// ---------------- device scratch ----------------
__device__ float4 g_hlin4[NNc*HIDc/4];    // xn @ W1 (pre-aggregation)
__device__ float4 g_hagg4[NNc*HIDc/4];    // scatter accumulator
__device__ float4 g_s4[NNc*KCc/4];        // softmax assignments
#define g_hlin ((float*)g_hlin4)
#define g_hagg ((float*)g_hagg4)
#define g_s    ((float*)g_s4)

__device__ int   g_src[EEc];
__device__ int   g_dst[EEc];
__device__ int   g_is64;

__device__ float g_gnsum[Bg*CINc];        // partial sums for GraphNorm
__device__ float g_gnsq[Bg*CINc];
__device__ float g_shift[Bg*CINc];
__device__ float g_scale[Bg*CINc];
__device__ float g_dis[NNc];              // rsqrt(in_deg + 1)
__device__ float g_degdst[NNc];
__device__ float g_degsrc[NNc];           // DMoN degrees (out-degree)
__device__ float g_ecount[Bg];
__device__ float g_trace[Bg];             // sum_e dot(s_src, s_dst)
__device__ float g_sx[Bg*KCc*HIDc];       // S^T X per graph
__device__ float g_ss[Bg*KCc*KCc];        // S^T S per graph
__device__ float g_ca[Bg*KCc];            // S^T degrees
__device__ float g_cs[Bg*KCc];            // cluster sizes

// ---------------- K0: zero accumulators (must run before convert) ----------------
__global__ __launch_bounds__(256) void k_zero() {
    int i0 = blockIdx.x * blockDim.x + threadIdx.x;
    int stride = gridDim.x * blockDim.x;
    float4 z4 = make_float4(0.f, 0.f, 0.f, 0.f);
    for (int i = i0; i < NNc*HIDc/4; i += stride) g_hagg4[i] = z4;
    for (int i = i0; i < NNc; i += stride) { g_degdst[i] = 0.f; g_degsrc[i] = 0.f; }
    for (int i = i0; i < Bg*KCc*HIDc; i += stride) g_sx[i] = 0.f;
    for (int i = i0; i < Bg*KCc*KCc; i += stride) g_ss[i] = 0.f;
    for (int i = i0; i < Bg*KCc; i += stride) { g_ca[i] = 0.f; g_cs[i] = 0.f; }
    for (int i = i0; i < Bg*CINc; i += stride) { g_gnsum[i] = 0.f; g_gnsq[i] = 0.f; }
    if (i0 < Bg) { g_ecount[i0] = 0.f; g_trace[i0] = 0.f; }
}

// ---------------- K_detect: is the edge buffer int64 or int32? ----------------
// Node ids < 2^15, so if int64, every odd 32-bit word (hi half) is 0.
__global__ __launch_bounds__(256) void k_detect(const int* __restrict__ ebuf) {
    __shared__ int nz;
    if (threadIdx.x == 0) nz = 0;
    __syncthreads();
    if (ebuf[threadIdx.x * 2 + 1] != 0) atomicOr(&nz, 1);
    __syncthreads();
    if (threadIdx.x == 0) g_is64 = (nz == 0) ? 1 : 0;
}

// ---------------- K_convert: canonical int32 src/dst + fused degree histos ----------------
__global__ __launch_bounds__(256) void k_convert_deg(const void* __restrict__ ebuf) {
    __shared__ float ec[Bg];
    if (threadIdx.x < Bg) ec[threadIdx.x] = 0.f;
    __syncthreads();
    int e = blockIdx.x * 256 + threadIdx.x;
    int s, d;
    if (g_is64) {
        const long long* p = (const long long*)ebuf;
        s = (int)p[e] & (NNc - 1);
        d = (int)p[EEc + e] & (NNc - 1);
    } else {
        const int* p = (const int*)ebuf;
        s = p[e] & (NNc - 1);
        d = p[EEc + e] & (NNc - 1);
    }
    g_src[e] = s;
    g_dst[e] = d;
    atomicAdd(&g_degdst[d], 1.f);
    atomicAdd(&g_degsrc[s], 1.f);
    atomicAdd(&ec[s >> 11], 1.f);
    __syncthreads();
    if (threadIdx.x < Bg) atomicAdd(&g_ecount[threadIdx.x], ec[threadIdx.x]);
}

// ---------------- K1a: GraphNorm partial sums (full-chip parallel) ----------------
// grid (Bg, 16): 128 rows per block.
__global__ __launch_bounds__(256) void k_gn_part(const float* __restrict__ x) {
    __shared__ float ssum[256], ssq[256];
    int b = blockIdx.x;
    int c = threadIdx.x & 63, r0 = threadIdx.x >> 6;
    const float* xb = x + (size_t)b * NPGc * CINc + (size_t)blockIdx.y * 128 * CINc;
    float s = 0.f, q = 0.f;
    for (int r = r0; r < 128; r += 4) {
        float v = xb[r * CINc + c];
        s += v; q += v * v;
    }
    ssum[threadIdx.x] = s; ssq[threadIdx.x] = q;
    __syncthreads();
    if (threadIdx.x < 64) {
        s = ssum[c] + ssum[c+64] + ssum[c+128] + ssum[c+192];
        q = ssq[c] + ssq[c+64] + ssq[c+128] + ssq[c+192];
        atomicAdd(&g_gnsum[b*CINc + c], s);
        atomicAdd(&g_gnsq[b*CINc + c], q);
    }
}

// ---------------- K1b: GraphNorm finalize ----------------
__global__ __launch_bounds__(1024) void k_gn_final(const float* __restrict__ gnw,
                                                   const float* __restrict__ gms) {
    int i = threadIdx.x;           // 1024 = 16 graphs * 64 features
    int c = i & 63;
    float mean = g_gnsum[i] * (1.f / NPGc);
    float ms = gms[c];
    // var = E[(x - ms*mean)^2] = E[x^2] - 2*ms*mean*E[x] + (ms*mean)^2
    float var = g_gnsq[i] * (1.f / NPGc) - 2.f * ms * mean * mean + ms * ms * mean * mean;
    g_shift[i] = mean * ms;
    g_scale[i] = gnw[c] * rsqrtf(var + 1e-5f);
}

// ---------------- K2: GraphNorm apply + GEMM xn @ W1 -> g_hlin ----------------
__global__ __launch_bounds__(256) void k_gemm1(const float* __restrict__ x,
                                               const float* __restrict__ gnb,
                                               const float* __restrict__ W1) {
    __shared__ float Ws[CINc][HIDc];     // 32 KB
    __shared__ float Xs[32][CINc + 1];   // 8.1 KB
    int n0 = blockIdx.x * 32;
    int b = n0 / NPGc;
    for (int i = threadIdx.x; i < 32 * CINc; i += 256) {
        int r = i >> 6, c = i & 63;
        float v = x[(size_t)(n0 + r) * CINc + c];
        Xs[r][c] = (v - g_shift[b*CINc + c]) * g_scale[b*CINc + c] + gnb[c];
    }
    for (int i = threadIdx.x; i < CINc * HIDc; i += 256)
        Ws[i >> 7][i & 127] = W1[i];
    __syncthreads();

    int q = threadIdx.x & 7;
    int jg = threadIdx.x >> 3;
    float acc[4][4];
#pragma unroll
    for (int i = 0; i < 4; i++)
#pragma unroll
        for (int j = 0; j < 4; j++) acc[i][j] = 0.f;

    for (int k = 0; k < CINc; k++) {
        float a0 = Xs[q*4+0][k], a1 = Xs[q*4+1][k], a2 = Xs[q*4+2][k], a3 = Xs[q*4+3][k];
        float w0 = Ws[k][jg*4+0], w1 = Ws[k][jg*4+1], w2 = Ws[k][jg*4+2], w3 = Ws[k][jg*4+3];
        acc[0][0] += a0*w0; acc[0][1] += a0*w1; acc[0][2] += a0*w2; acc[0][3] += a0*w3;
        acc[1][0] += a1*w0; acc[1][1] += a1*w1; acc[1][2] += a1*w2; acc[1][3] += a1*w3;
        acc[2][0] += a2*w0; acc[2][1] += a2*w1; acc[2][2] += a2*w2; acc[2][3] += a2*w3;
        acc[3][0] += a3*w0; acc[3][1] += a3*w1; acc[3][2] += a3*w2; acc[3][3] += a3*w3;
    }
#pragma unroll
    for (int i = 0; i < 4; i++)
#pragma unroll
        for (int j = 0; j < 4; j++)
            g_hlin[(size_t)(n0 + q*4 + i) * HIDc + jg*4 + j] = acc[i][j];
}

// ---------------- K4: dis = rsqrt(deg_in + 1) ----------------
__global__ __launch_bounds__(256) void k_dis() {
    int i = blockIdx.x * 256 + threadIdx.x;
    if (i < NNc) g_dis[i] = rsqrtf(g_degdst[i] + 1.f);
}

// ---------------- K5: edge scatter (the hot loop) ----------------
__global__ __launch_bounds__(256) void k_scatter() {
    int w = (blockIdx.x * 256 + threadIdx.x) >> 5;
    int lane = threadIdx.x & 31;
    if (w >= EEc) return;
    int s = g_src[w];
    int d = g_dst[w];
    float c = g_dis[s] * g_dis[d];
    float4 v = g_hlin4[(size_t)s * (HIDc/4) + lane];
    float4* out = &g_hagg4[(size_t)d * (HIDc/4) + lane];
    asm volatile("red.global.add.v4.f32 [%0], {%1,%2,%3,%4};"
                 :: "l"(out), "f"(v.x*c), "f"(v.y*c), "f"(v.z*c), "f"(v.w*c)
                 : "memory");
}

// ---------------- K6: fused finalize-h + selection-softmax + node reductions ----------------
// grid (Bg, 16): 128 nodes per block, processed in 8 tiles of 16 nodes.
// Eliminates the g_h round-trip (32 MB) and cuts Wp traffic 16x.
__global__ __launch_bounds__(256) void k_fin_red(const float* __restrict__ b1,
                                                 const float* __restrict__ Wp,
                                                 const float* __restrict__ bp,
                                                 float* __restrict__ out_s) {
    __shared__ float Wps[HIDc * KCc];  // 16 KB
    __shared__ float sH[16][HIDc];     // 8 KB
    __shared__ float sS[16][KCc];      // 2 KB
    __shared__ float sD[16];
    __shared__ float b1s[HIDc];
    __shared__ float bps[KCc];
    int tid = threadIdx.x;
    int b = blockIdx.x;
    int n0 = b * NPGc + blockIdx.y * 128;
    for (int i = tid; i < HIDc * KCc; i += 256) Wps[i] = Wp[i];
    if (tid < HIDc) b1s[tid] = b1[tid];
    if (tid < KCc)  bps[tid] = bp[tid];

    int warp = tid >> 5, lane = tid & 31;
    int k = tid >> 3, j8 = tid & 7;
    float accx[16];
#pragma unroll
    for (int i = 0; i < 16; i++) accx[i] = 0.f;
    float accss[4] = {0.f, 0.f, 0.f, 0.f};
    float accca = 0.f, acccs = 0.f;

    for (int tile = 0; tile < 8; tile++) {
        int base = n0 + tile * 16;
        __syncthreads();   // protect smem from previous tile's readers
        // --- compute h for 16 nodes into smem (self-loop + bias + relu) ---
        for (int idx = tid; idx < 16 * HIDc; idx += 256) {
            int nl = idx >> 7, j = idx & 127;
            int n = base + nl;
            float dis = g_dis[n];
            float v = g_hagg[(size_t)n*HIDc + j]
                    + dis * dis * g_hlin[(size_t)n*HIDc + j] + b1s[j];
            sH[nl][j] = fmaxf(v, 0.f);
        }
        if (tid < 16) sD[tid] = g_degsrc[base + tid];
        __syncthreads();
        // --- selection softmax: warp w handles nodes 2w, 2w+1 of the tile ---
#pragma unroll
        for (int u = 0; u < 2; u++) {
            int nl = warp * 2 + u;
            float acc = bps[lane];
#pragma unroll 8
            for (int j = 0; j < HIDc; j++)
                acc += sH[nl][j] * Wps[j * KCc + lane];
            float m = acc;
#pragma unroll
            for (int o = 16; o; o >>= 1) m = fmaxf(m, __shfl_xor_sync(0xffffffffu, m, o));
            float e = expf(acc - m);
            float sum = e;
#pragma unroll
            for (int o = 16; o; o >>= 1) sum += __shfl_xor_sync(0xffffffffu, sum, o);
            float sv = e / sum;
            sS[nl][lane] = sv;
            int n = base + nl;
            g_s[n*KCc + lane] = sv;
            out_s[n*KCc + lane] = sv;
        }
        __syncthreads();
        // --- accumulate S^T H, S^T S, ca, cs over the tile ---
#pragma unroll 4
        for (int nn = 0; nn < 16; nn++) {
            float sk = sS[nn][k];
#pragma unroll
            for (int jj = 0; jj < 16; jj++)
                accx[jj] += sk * sH[nn][j8 + jj * 8];
#pragma unroll
            for (int i = 0; i < 4; i++) {
                int idx = tid * 4 + i;
                accss[i] += sS[nn][idx >> 5] * sS[nn][idx & 31];
            }
            if (tid < 32) {
                float sv = sS[nn][tid];
                accca += sv * sD[nn];
                acccs += sv;
            }
        }
    }
#pragma unroll
    for (int jj = 0; jj < 16; jj++)
        atomicAdd(&g_sx[b*KCc*HIDc + k*HIDc + j8 + jj*8], accx[jj]);
#pragma unroll
    for (int i = 0; i < 4; i++)
        atomicAdd(&g_ss[b*KCc*KCc + tid*4 + i], accss[i]);
    if (tid < 32) {
        atomicAdd(&g_ca[b*KCc + tid], accca);
        atomicAdd(&g_cs[b*KCc + tid], acccs);
    }
}

// ---------------- K7: spectral trace = sum_e dot(s_src, s_dst) per graph ----------------
__global__ __launch_bounds__(256) void k_trace() {
    __shared__ float sacc[Bg];
    if (threadIdx.x < Bg) sacc[threadIdx.x] = 0.f;
    __syncthreads();
    int wg = (blockIdx.x * 256 + threadIdx.x) >> 5;
    int lane = threadIdx.x & 31;
    for (int t = 0; t < 16; t++) {
        int e = wg * 16 + t;
        int sn = g_src[e];
        int dn = g_dst[e];
        float p = g_s[sn*KCc + lane] * g_s[dn*KCc + lane];
#pragma unroll
        for (int o = 16; o; o >>= 1) p += __shfl_xor_sync(0xffffffffu, p, o);
        if (lane == 0) atomicAdd(&sacc[sn >> 11], p);
    }
    __syncthreads();
    if (threadIdx.x < Bg) atomicAdd(&g_trace[threadIdx.x], sacc[threadIdx.x]);
}

// ---------------- K9: losses ----------------
__global__ __launch_bounds__(512) void k_losses(float* __restrict__ out_loss) {
    __shared__ float bl[Bg];
    int w = threadIdx.x >> 5, lane = threadIdx.x & 31;
    if (w < Bg) {
        int b = w;
        float m = g_ecount[b] * 0.5f;
        float q = 0.f;
        for (int i = 0; i < 32; i++) {
            float v = g_ss[b*1024 + i*32 + lane];
            q += v * v;
        }
#pragma unroll
        for (int o = 16; o; o >>= 1) q += __shfl_xor_sync(0xffffffffu, q, o);
        float nrm = sqrtf(q);
        float inv_sk = rsqrtf((float)KCc);
        float oo = 0.f;
        for (int i = 0; i < 32; i++) {
            float v = g_ss[b*1024 + i*32 + lane] / nrm - ((i == lane) ? inv_sk : 0.f);
            oo += v * v;
        }
#pragma unroll
        for (int o = 16; o; o >>= 1) oo += __shfl_xor_sync(0xffffffffu, oo, o);
        float cav = g_ca[b*KCc + lane];
        float ca2 = cav * cav;
#pragma unroll
        for (int o = 16; o; o >>= 1) ca2 += __shfl_xor_sync(0xffffffffu, ca2, o);
        float csv = g_cs[b*KCc + lane];
        float cs2 = csv * csv;
#pragma unroll
        for (int o = 16; o; o >>= 1) cs2 += __shfl_xor_sync(0xffffffffu, cs2, o);
        if (lane == 0) {
            float spec = -(g_trace[b] - ca2 / (2.f * m)) / (2.f * m);
            float ortho = sqrtf(oo);
            float clus = sqrtf(cs2) / (float)NPGc * sqrtf((float)KCc) - 1.f;
            bl[b] = spec + ortho + clus;
        }
    }
    __syncthreads();
    if (threadIdx.x == 0) {
        float t = 0.f;
        for (int i = 0; i < Bg; i++) t += bl[i];
        out_loss[0] = t / (float)Bg;
    }
}

// ---------------- K10: selu + log_softmax of out_x ----------------
__global__ __launch_bounds__(128) void k_outx(float* __restrict__ out) {
    __shared__ float redm[4], reds[4];
    int row = blockIdx.x;
    int t = threadIdx.x;
    int warp = t >> 5, lane = t & 31;
    float v = g_sx[row * HIDc + t];
    const float sc = 1.0507009873554805f, al = 1.6732632423543772f;
    v = (v > 0.f) ? sc * v : sc * al * (expf(v) - 1.f);
    float mx = v;
#pragma unroll
    for (int o = 16; o; o >>= 1) mx = fmaxf(mx, __shfl_xor_sync(0xffffffffu, mx, o));
    if (lane == 0) redm[warp] = mx;
    __syncthreads();
    mx = fmaxf(fmaxf(redm[0], redm[1]), fmaxf(redm[2], redm[3]));
    float e = expf(v - mx);
    float sum = e;
#pragma unroll
    for (int o = 16; o; o >>= 1) sum += __shfl_xor_sync(0xffffffffu, sum, o);
    if (lane == 0) reds[warp] = sum;
    __syncthreads();
    sum = reds[0] + reds[1] + reds[2] + reds[3];
    out[row * HIDc + t] = v - mx - logf(sum);
}

// ---------------- launch ----------------
extern "C" void kernel_launch(void* const* d_in, const int* in_sizes, int n_in,
                              void* d_out, int out_size) {
    int i_x = 0, i_W1 = 4, i_b1 = 5, i_Wp = 6, i_bp = 7, i_ei = 8;
    for (int i = 0; i < n_in; i++) {
        int sz = in_sizes[i];
        if (sz == NNc * CINc)       i_x  = i;   // 2097152
        else if (sz == CINc * HIDc) i_W1 = i;   // 8192
        else if (sz == HIDc)        i_b1 = i;   // 128
        else if (sz == HIDc * KCc)  i_Wp = i;   // 4096
        else if (sz == KCc)         i_bp = i;   // 32
        else if (sz == 2 * EEc)     i_ei = i;   // 1048576
    }
    const float* x   = (const float*)d_in[i_x];
    const float* gnw = (const float*)d_in[1];
    const float* gnb = (const float*)d_in[2];
    const float* gms = (const float*)d_in[3];
    const float* W1  = (const float*)d_in[i_W1];
    const float* b1  = (const float*)d_in[i_b1];
    const float* Wp  = (const float*)d_in[i_Wp];
    const float* bp  = (const float*)d_in[i_bp];
    const void*  ei  = d_in[i_ei];

    float* out = (float*)d_out;
    float* out_loss = out + Bg*KCc*HIDc;          // 65536
    float* out_s    = out + Bg*KCc*HIDc + 1;      // 65537

    k_zero<<<4096, 256>>>();
    k_detect<<<1, 256>>>((const int*)ei);
    k_convert_deg<<<EEc/256, 256>>>(ei);
    k_gn_part<<<dim3(Bg, 16), 256>>>(x);
    k_gn_final<<<1, 1024>>>(gnw, gms);
    k_gemm1<<<NNc/32, 256>>>(x, gnb, W1);
    k_dis<<<NNc/256, 256>>>();
    k_scatter<<<EEc*32/256, 256>>>();
    k_fin_red<<<dim3(Bg, 16), 256>>>(b1, Wp, bp, out_s);
    k_trace<<<EEc/16/8, 256>>>();
    k_losses<<<1, 512>>>(out_loss);
    k_outx<<<Bg*KCc, 128>>>(out);
}

// round 6
// speedup vs baseline: 1.2549x; 1.1163x over previous
#include <cuda_runtime.h>

// Problem constants
#define Bg    16
#define NPGc  2048
#define NNc   32768      // Bg * NPGc
#define CINc  64
#define HIDc  128
#define KCc   32
#define EEc   524288

// ---------------- device scratch ----------------
__device__ float4 g_hlin4[NNc*HIDc/4];    // xn @ W1 (pre-aggregation)
__device__ float4 g_hagg4[NNc*HIDc/4];    // aggregated neighbor sums (plain stores)
__device__ float4 g_s4[NNc*KCc/4];        // softmax assignments
#define g_hlin ((float*)g_hlin4)
#define g_hagg ((float*)g_hagg4)
#define g_s    ((float*)g_s4)

__device__ int   g_src[EEc];
__device__ int   g_dst[EEc];
__device__ int   g_csrc[EEc];             // CSR column (src) indices, grouped by dst
__device__ int   g_degi[NNc];             // in-degree (int)
__device__ int   g_rowptr[NNc];           // CSR row starts (exclusive scan of degi)
__device__ int   g_cursor[NNc];           // fill cursors
__device__ int   g_bsum[256];             // scan partials
__device__ int   g_boff[256];
__device__ int   g_is64;

__device__ float g_gnsum[Bg*CINc];
__device__ float g_gnsq[Bg*CINc];
__device__ float g_shift[Bg*CINc];
__device__ float g_scale[Bg*CINc];
__device__ float g_dis[NNc];              // rsqrt(in_deg + 1)
__device__ float g_degsrc[NNc];           // DMoN degrees (out-degree)
__device__ float g_ecount[Bg];
__device__ float g_trace[Bg];             // sum_e dot(s_src, s_dst)
__device__ float g_sx[Bg*KCc*HIDc];       // S^T X per graph
__device__ float g_ss[Bg*KCc*KCc];        // S^T S per graph
__device__ float g_ca[Bg*KCc];            // S^T degrees
__device__ float g_cs[Bg*KCc];            // cluster sizes

// ---------------- f32x2 helpers (Blackwell packed fp32) ----------------
__device__ __forceinline__ unsigned long long f2pack(float x, float y) {
    unsigned long long r;
    asm("mov.b64 %0, {%1, %2};" : "=l"(r) : "f"(x), "f"(y));
    return r;
}
__device__ __forceinline__ unsigned long long ffma2(unsigned long long a,
                                                    unsigned long long b,
                                                    unsigned long long c) {
    unsigned long long d;
    asm("fma.rn.f32x2 %0, %1, %2, %3;" : "=l"(d) : "l"(a), "l"(b), "l"(c));
    return d;
}
__device__ __forceinline__ float2 f2unpack(unsigned long long v) {
    float2 f;
    asm("mov.b64 {%0, %1}, %2;" : "=f"(f.x), "=f"(f.y) : "l"(v));
    return f;
}

// ---------------- K0: zero small accumulators ----------------
__global__ __launch_bounds__(256) void k_zero() {
    int i0 = blockIdx.x * blockDim.x + threadIdx.x;
    int stride = gridDim.x * blockDim.x;
    for (int i = i0; i < NNc; i += stride) { g_degi[i] = 0; g_degsrc[i] = 0.f; }
    for (int i = i0; i < Bg*KCc*HIDc; i += stride) g_sx[i] = 0.f;
    for (int i = i0; i < Bg*KCc*KCc; i += stride) g_ss[i] = 0.f;
    for (int i = i0; i < Bg*KCc; i += stride) { g_ca[i] = 0.f; g_cs[i] = 0.f; }
    for (int i = i0; i < Bg*CINc; i += stride) { g_gnsum[i] = 0.f; g_gnsq[i] = 0.f; }
    if (i0 < Bg) { g_ecount[i0] = 0.f; g_trace[i0] = 0.f; }
}

// ---------------- K_detect: int64 vs int32 edge buffer ----------------
__global__ __launch_bounds__(256) void k_detect(const int* __restrict__ ebuf) {
    __shared__ int nz;
    if (threadIdx.x == 0) nz = 0;
    __syncthreads();
    if (ebuf[threadIdx.x * 2 + 1] != 0) atomicOr(&nz, 1);
    __syncthreads();
    if (threadIdx.x == 0) g_is64 = (nz == 0) ? 1 : 0;
}

// ---------------- K_convert: canonical src/dst + degree histograms ----------------
__global__ __launch_bounds__(256) void k_convert_deg(const void* __restrict__ ebuf) {
    __shared__ float ec[Bg];
    if (threadIdx.x < Bg) ec[threadIdx.x] = 0.f;
    __syncthreads();
    int e = blockIdx.x * 256 + threadIdx.x;
    int s, d;
    if (g_is64) {
        const long long* p = (const long long*)ebuf;
        s = (int)p[e] & (NNc - 1);
        d = (int)p[EEc + e] & (NNc - 1);
    } else {
        const int* p = (const int*)ebuf;
        s = p[e] & (NNc - 1);
        d = p[EEc + e] & (NNc - 1);
    }
    g_src[e] = s;
    g_dst[e] = d;
    atomicAdd(&g_degi[d], 1);
    atomicAdd(&g_degsrc[s], 1.f);
    atomicAdd(&ec[s >> 11], 1.f);
    __syncthreads();
    if (threadIdx.x < Bg) atomicAdd(&g_ecount[threadIdx.x], ec[threadIdx.x]);
}

// ---------------- prefix scan (3 tiny passes) -> g_rowptr, g_cursor ----------------
__global__ __launch_bounds__(128) void k_scan1() {        // grid 256
    __shared__ int sm[128];
    int t = threadIdx.x;
    sm[t] = g_degi[blockIdx.x * 128 + t];
    __syncthreads();
    for (int o = 64; o > 0; o >>= 1) {
        if (t < o) sm[t] += sm[t + o];
        __syncthreads();
    }
    if (t == 0) g_bsum[blockIdx.x] = sm[0];
}
__global__ __launch_bounds__(256) void k_scan2() {        // 1 block
    __shared__ int sm[256];
    int t = threadIdx.x;
    int own = g_bsum[t];
    sm[t] = own;
    __syncthreads();
    for (int o = 1; o < 256; o <<= 1) {
        int add = (t >= o) ? sm[t - o] : 0;
        __syncthreads();
        sm[t] += add;
        __syncthreads();
    }
    g_boff[t] = sm[t] - own;   // exclusive
}
__global__ __launch_bounds__(128) void k_scan3() {        // grid 256
    __shared__ int sm[128];
    int t = threadIdx.x;
    int n = blockIdx.x * 128 + t;
    int d = g_degi[n];
    sm[t] = d;
    __syncthreads();
    for (int o = 1; o < 128; o <<= 1) {
        int add = (t >= o) ? sm[t - o] : 0;
        __syncthreads();
        sm[t] += add;
        __syncthreads();
    }
    int excl = sm[t] - d + g_boff[blockIdx.x];
    g_rowptr[n] = excl;
    g_cursor[n] = excl;
}

// ---------------- K_fill: scatter edge srcs into CSR slots ----------------
__global__ __launch_bounds__(256) void k_fill() {
    int e = blockIdx.x * 256 + threadIdx.x;
    int d = g_dst[e];
    int pos = atomicAdd(&g_cursor[d], 1);
    g_csrc[pos] = g_src[e];
}

// ---------------- K1a: GraphNorm partial sums ----------------
__global__ __launch_bounds__(256) void k_gn_part(const float* __restrict__ x) {
    __shared__ float ssum[256], ssq[256];
    int b = blockIdx.x;
    int c = threadIdx.x & 63, r0 = threadIdx.x >> 6;
    const float* xb = x + (size_t)b * NPGc * CINc + (size_t)blockIdx.y * 128 * CINc;
    float s = 0.f, q = 0.f;
    for (int r = r0; r < 128; r += 4) {
        float v = xb[r * CINc + c];
        s += v; q += v * v;
    }
    ssum[threadIdx.x] = s; ssq[threadIdx.x] = q;
    __syncthreads();
    if (threadIdx.x < 64) {
        s = ssum[c] + ssum[c+64] + ssum[c+128] + ssum[c+192];
        q = ssq[c] + ssq[c+64] + ssq[c+128] + ssq[c+192];
        atomicAdd(&g_gnsum[b*CINc + c], s);
        atomicAdd(&g_gnsq[b*CINc + c], q);
    }
}

// ---------------- K1b: GraphNorm finalize ----------------
__global__ __launch_bounds__(1024) void k_gn_final(const float* __restrict__ gnw,
                                                   const float* __restrict__ gms) {
    int i = threadIdx.x;           // 16 graphs * 64 features
    int c = i & 63;
    float mean = g_gnsum[i] * (1.f / NPGc);
    float ms = gms[c];
    float var = g_gnsq[i] * (1.f / NPGc) - 2.f * ms * mean * mean + ms * ms * mean * mean;
    g_shift[i] = mean * ms;
    g_scale[i] = gnw[c] * rsqrtf(var + 1e-5f);
}

// ---------------- K2: GraphNorm apply + GEMM xn @ W1 (f32x2 packed) ----------------
__global__ __launch_bounds__(256) void k_gemm1(const float* __restrict__ x,
                                               const float* __restrict__ gnb,
                                               const float* __restrict__ W1) {
    __shared__ float Ws[CINc][HIDc];     // 32 KB
    __shared__ float Xs[32][CINc + 1];   // 8.1 KB
    int n0 = blockIdx.x * 32;
    int b = n0 / NPGc;
    for (int i = threadIdx.x; i < 32 * CINc; i += 256) {
        int r = i >> 6, c = i & 63;
        float v = x[(size_t)(n0 + r) * CINc + c];
        Xs[r][c] = (v - g_shift[b*CINc + c]) * g_scale[b*CINc + c] + gnb[c];
    }
    for (int i = threadIdx.x; i < CINc * HIDc; i += 256)
        Ws[i >> 7][i & 127] = W1[i];
    __syncthreads();

    int q = threadIdx.x & 7;     // node quad (4 nodes)
    int jg = threadIdx.x >> 3;   // output group (4 outputs = 2 f32x2 pairs)
    unsigned long long acc2[4][2];
#pragma unroll
    for (int i = 0; i < 4; i++) { acc2[i][0] = 0ull; acc2[i][1] = 0ull; }

    for (int k = 0; k < CINc; k++) {
        unsigned long long w01 = *(const unsigned long long*)&Ws[k][jg*4];
        unsigned long long w23 = *(const unsigned long long*)&Ws[k][jg*4+2];
#pragma unroll
        for (int i = 0; i < 4; i++) {
            float a = Xs[q*4+i][k];
            unsigned long long a2 = f2pack(a, a);
            acc2[i][0] = ffma2(a2, w01, acc2[i][0]);
            acc2[i][1] = ffma2(a2, w23, acc2[i][1]);
        }
    }
#pragma unroll
    for (int i = 0; i < 4; i++) {
        float2 f01 = f2unpack(acc2[i][0]);
        float2 f23 = f2unpack(acc2[i][1]);
        g_hlin4[(size_t)(n0 + q*4 + i) * (HIDc/4) + jg] =
            make_float4(f01.x, f01.y, f23.x, f23.y);
    }
}

// ---------------- K4: dis = rsqrt(deg_in + 1) ----------------
__global__ __launch_bounds__(256) void k_dis() {
    int i = blockIdx.x * 256 + threadIdx.x;
    if (i < NNc) g_dis[i] = rsqrtf((float)g_degi[i] + 1.f);
}

// ---------------- K5: CSR gather (replaces atomic scatter) ----------------
// One warp per destination node; register accumulation, single 512B store.
__global__ __launch_bounds__(256) void k_gather() {
    int n = (blockIdx.x * 256 + threadIdx.x) >> 5;
    int lane = threadIdx.x & 31;
    if (n >= NNc) return;
    int rs  = g_rowptr[n];
    int deg = g_degi[n];
    float disd = g_dis[n];
    float4 acc = make_float4(0.f, 0.f, 0.f, 0.f);
#pragma unroll 4
    for (int i = 0; i < deg; i++) {
        int s = g_csrc[rs + i];
        float c = disd * g_dis[s];
        float4 v = g_hlin4[(size_t)s * (HIDc/4) + lane];
        acc.x += c * v.x; acc.y += c * v.y; acc.z += c * v.z; acc.w += c * v.w;
    }
    g_hagg4[(size_t)n * (HIDc/4) + lane] = acc;
}

// ---------------- K6: fused finalize-h + selection-softmax + node reductions ----------------
__global__ __launch_bounds__(256) void k_fin_red(const float* __restrict__ b1,
                                                 const float* __restrict__ Wp,
                                                 const float* __restrict__ bp,
                                                 float* __restrict__ out_s) {
    __shared__ float Wps[HIDc * KCc];  // 16 KB
    __shared__ float sH[16][HIDc];     // 8 KB
    __shared__ float sS[16][KCc];      // 2 KB
    __shared__ float sD[16];
    __shared__ float b1s[HIDc];
    __shared__ float bps[KCc];
    int tid = threadIdx.x;
    int b = blockIdx.x;
    int n0 = b * NPGc + blockIdx.y * 128;
    for (int i = tid; i < HIDc * KCc; i += 256) Wps[i] = Wp[i];
    if (tid < HIDc) b1s[tid] = b1[tid];
    if (tid < KCc)  bps[tid] = bp[tid];

    int warp = tid >> 5, lane = tid & 31;
    int k = tid >> 3, j8 = tid & 7;
    float accx[16];
#pragma unroll
    for (int i = 0; i < 16; i++) accx[i] = 0.f;
    float accss[4] = {0.f, 0.f, 0.f, 0.f};
    float accca = 0.f, acccs = 0.f;

    for (int tile = 0; tile < 8; tile++) {
        int base = n0 + tile * 16;
        __syncthreads();
        for (int idx = tid; idx < 16 * HIDc; idx += 256) {
            int nl = idx >> 7, j = idx & 127;
            int n = base + nl;
            float dis = g_dis[n];
            float v = g_hagg[(size_t)n*HIDc + j]
                    + dis * dis * g_hlin[(size_t)n*HIDc + j] + b1s[j];
            sH[nl][j] = fmaxf(v, 0.f);
        }
        if (tid < 16) sD[tid] = g_degsrc[base + tid];
        __syncthreads();
#pragma unroll
        for (int u = 0; u < 2; u++) {
            int nl = warp * 2 + u;
            float acc = bps[lane];
#pragma unroll 8
            for (int j = 0; j < HIDc; j++)
                acc += sH[nl][j] * Wps[j * KCc + lane];
            float m = acc;
#pragma unroll
            for (int o = 16; o; o >>= 1) m = fmaxf(m, __shfl_xor_sync(0xffffffffu, m, o));
            float e = expf(acc - m);
            float sum = e;
#pragma unroll
            for (int o = 16; o; o >>= 1) sum += __shfl_xor_sync(0xffffffffu, sum, o);
            float sv = e / sum;
            sS[nl][lane] = sv;
            int n = base + nl;
            g_s[n*KCc + lane] = sv;
            out_s[n*KCc + lane] = sv;
        }
        __syncthreads();
#pragma unroll 4
        for (int nn = 0; nn < 16; nn++) {
            float sk = sS[nn][k];
#pragma unroll
            for (int jj = 0; jj < 16; jj++)
                accx[jj] += sk * sH[nn][j8 + jj * 8];
#pragma unroll
            for (int i = 0; i < 4; i++) {
                int idx = tid * 4 + i;
                accss[i] += sS[nn][idx >> 5] * sS[nn][idx & 31];
            }
            if (tid < 32) {
                float sv = sS[nn][tid];
                accca += sv * sD[nn];
                acccs += sv;
            }
        }
    }
#pragma unroll
    for (int jj = 0; jj < 16; jj++)
        atomicAdd(&g_sx[b*KCc*HIDc + k*HIDc + j8 + jj*8], accx[jj]);
#pragma unroll
    for (int i = 0; i < 4; i++)
        atomicAdd(&g_ss[b*KCc*KCc + tid*4 + i], accss[i]);
    if (tid < 32) {
        atomicAdd(&g_ca[b*KCc + tid], accca);
        atomicAdd(&g_cs[b*KCc + tid], acccs);
    }
}

// ---------------- K7: spectral trace per graph ----------------
__global__ __launch_bounds__(256) void k_trace() {
    __shared__ float sacc[Bg];
    if (threadIdx.x < Bg) sacc[threadIdx.x] = 0.f;
    __syncthreads();
    int wg = (blockIdx.x * 256 + threadIdx.x) >> 5;
    int lane = threadIdx.x & 31;
    for (int t = 0; t < 16; t++) {
        int e = wg * 16 + t;
        int sn = g_src[e];
        int dn = g_dst[e];
        float p = g_s[sn*KCc + lane] * g_s[dn*KCc + lane];
#pragma unroll
        for (int o = 16; o; o >>= 1) p += __shfl_xor_sync(0xffffffffu, p, o);
        if (lane == 0) atomicAdd(&sacc[sn >> 11], p);
    }
    __syncthreads();
    if (threadIdx.x < Bg) atomicAdd(&g_trace[threadIdx.x], sacc[threadIdx.x]);
}

// ---------------- K9: losses ----------------
__global__ __launch_bounds__(512) void k_losses(float* __restrict__ out_loss) {
    __shared__ float bl[Bg];
    int w = threadIdx.x >> 5, lane = threadIdx.x & 31;
    if (w < Bg) {
        int b = w;
        float m = g_ecount[b] * 0.5f;
        float q = 0.f;
        for (int i = 0; i < 32; i++) {
            float v = g_ss[b*1024 + i*32 + lane];
            q += v * v;
        }
#pragma unroll
        for (int o = 16; o; o >>= 1) q += __shfl_xor_sync(0xffffffffu, q, o);
        float nrm = sqrtf(q);
        float inv_sk = rsqrtf((float)KCc);
        float oo = 0.f;
        for (int i = 0; i < 32; i++) {
            float v = g_ss[b*1024 + i*32 + lane] / nrm - ((i == lane) ? inv_sk : 0.f);
            oo += v * v;
        }
#pragma unroll
        for (int o = 16; o; o >>= 1) oo += __shfl_xor_sync(0xffffffffu, oo, o);
        float cav = g_ca[b*KCc + lane];
        float ca2 = cav * cav;
#pragma unroll
        for (int o = 16; o; o >>= 1) ca2 += __shfl_xor_sync(0xffffffffu, ca2, o);
        float csv = g_cs[b*KCc + lane];
        float cs2 = csv * csv;
#pragma unroll
        for (int o = 16; o; o >>= 1) cs2 += __shfl_xor_sync(0xffffffffu, cs2, o);
        if (lane == 0) {
            float spec = -(g_trace[b] - ca2 / (2.f * m)) / (2.f * m);
            float ortho = sqrtf(oo);
            float clus = sqrtf(cs2) / (float)NPGc * sqrtf((float)KCc) - 1.f;
            bl[b] = spec + ortho + clus;
        }
    }
    __syncthreads();
    if (threadIdx.x == 0) {
        float t = 0.f;
        for (int i = 0; i < Bg; i++) t += bl[i];
        out_loss[0] = t / (float)Bg;
    }
}

// ---------------- K10: selu + log_softmax of out_x ----------------
__global__ __launch_bounds__(128) void k_outx(float* __restrict__ out) {
    __shared__ float redm[4], reds[4];
    int row = blockIdx.x;
    int t = threadIdx.x;
    int warp = t >> 5, lane = t & 31;
    float v = g_sx[row * HIDc + t];
    const float sc = 1.0507009873554805f, al = 1.6732632423543772f;
    v = (v > 0.f) ? sc * v : sc * al * (expf(v) - 1.f);
    float mx = v;
#pragma unroll
    for (int o = 16; o; o >>= 1) mx = fmaxf(mx, __shfl_xor_sync(0xffffffffu, mx, o));
    if (lane == 0) redm[warp] = mx;
    __syncthreads();
    mx = fmaxf(fmaxf(redm[0], redm[1]), fmaxf(redm[2], redm[3]));
    float e = expf(v - mx);
    float sum = e;
#pragma unroll
    for (int o = 16; o; o >>= 1) sum += __shfl_xor_sync(0xffffffffu, sum, o);
    if (lane == 0) reds[warp] = sum;
    __syncthreads();
    sum = reds[0] + reds[1] + reds[2] + reds[3];
    out[row * HIDc + t] = v - mx - logf(sum);
}

// ---------------- launch ----------------
extern "C" void kernel_launch(void* const* d_in, const int* in_sizes, int n_in,
                              void* d_out, int out_size) {
    int i_x = 0, i_W1 = 4, i_b1 = 5, i_Wp = 6, i_bp = 7, i_ei = 8;
    for (int i = 0; i < n_in; i++) {
        int sz = in_sizes[i];
        if (sz == NNc * CINc)       i_x  = i;
        else if (sz == CINc * HIDc) i_W1 = i;
        else if (sz == HIDc)        i_b1 = i;
        else if (sz == HIDc * KCc)  i_Wp = i;
        else if (sz == KCc)         i_bp = i;
        else if (sz == 2 * EEc)     i_ei = i;
    }
    const float* x   = (const float*)d_in[i_x];
    const float* gnw = (const float*)d_in[1];
    const float* gnb = (const float*)d_in[2];
    const float* gms = (const float*)d_in[3];
    const float* W1  = (const float*)d_in[i_W1];
    const float* b1  = (const float*)d_in[i_b1];
    const float* Wp  = (const float*)d_in[i_Wp];
    const float* bp  = (const float*)d_in[i_bp];
    const void*  ei  = d_in[i_ei];

    float* out = (float*)d_out;
    float* out_loss = out + Bg*KCc*HIDc;          // 65536
    float* out_s    = out + Bg*KCc*HIDc + 1;      // 65537

    k_zero<<<1024, 256>>>();
    k_detect<<<1, 256>>>((const int*)ei);
    k_convert_deg<<<EEc/256, 256>>>(ei);
    k_scan1<<<256, 128>>>();
    k_scan2<<<1, 256>>>();
    k_scan3<<<256, 128>>>();
    k_dis<<<NNc/256, 256>>>();
    k_fill<<<EEc/256, 256>>>();
    k_gn_part<<<dim3(Bg, 16), 256>>>(x);
    k_gn_final<<<1, 1024>>>(gnw, gms);
    k_gemm1<<<NNc/32, 256>>>(x, gnb, W1);
    k_gather<<<NNc/8, 256>>>();
    k_fin_red<<<dim3(Bg, 16), 256>>>(b1, Wp, bp, out_s);
    k_trace<<<EEc/16/8, 256>>>();
    k_losses<<<1, 512>>>(out_loss);
    k_outx<<<Bg*KCc, 128>>>(out);
}

// round 8
// speedup vs baseline: 1.3301x; 1.0600x over previous
#include <cuda_runtime.h>

// Problem constants
#define Bg    16
#define NPGc  2048
#define NNc   32768      // Bg * NPGc
#define CINc  64
#define HIDc  128
#define KCc   32
#define EEc   524288

// ---------------- device scratch ----------------
__device__ float4 g_hlin4[NNc*HIDc/4];    // xn @ W1 (pre-aggregation)
__device__ float4 g_hagg4[NNc*HIDc/4];    // aggregated neighbor sums
#define g_hlin ((float*)g_hlin4)
#define g_hagg ((float*)g_hagg4)

__device__ int   g_src[EEc];
__device__ int   g_dst[EEc];
__device__ int   g_csrc[EEc];             // CSR column (src) indices, grouped by dst
__device__ int   g_degi[NNc];             // in-degree (int)
__device__ int   g_rowptr[NNc];           // CSR row starts
__device__ int   g_cursor[NNc];           // fill cursors
__device__ int   g_counter;               // scan base allocator

__device__ float g_gnsum[Bg*CINc];
__device__ float g_gnsq[Bg*CINc];
__device__ float g_dis[NNc];              // rsqrt(in_deg + 1)
__device__ float g_degsrc[NNc];           // DMoN degrees (out-degree)
__device__ float g_ecount[Bg];
__device__ float g_trace[Bg];             // sum_e dot(s_src, s_dst)
__device__ float g_sx[Bg*KCc*HIDc];       // S^T X per graph
__device__ float g_ss[Bg*KCc*KCc];        // S^T S per graph
__device__ float g_ca[Bg*KCc];            // S^T degrees
__device__ float g_cs[Bg*KCc];            // cluster sizes

// ---------------- f32x2 helpers (Blackwell packed fp32) ----------------
__device__ __forceinline__ unsigned long long f2pack(float x, float y) {
    unsigned long long r;
    asm("mov.b64 %0, {%1, %2};" : "=l"(r) : "f"(x), "f"(y));
    return r;
}
__device__ __forceinline__ unsigned long long ffma2(unsigned long long a,
                                                    unsigned long long b,
                                                    unsigned long long c) {
    unsigned long long d;
    asm("fma.rn.f32x2 %0, %1, %2, %3;" : "=l"(d) : "l"(a), "l"(b), "l"(c));
    return d;
}
__device__ __forceinline__ float2 f2unpack(unsigned long long v) {
    float2 f;
    asm("mov.b64 {%0, %1}, %2;" : "=f"(f.x), "=f"(f.y) : "l"(v));
    return f;
}

// ---------------- K0: zero small accumulators ----------------
__global__ __launch_bounds__(256) void k_zero() {
    int i0 = blockIdx.x * blockDim.x + threadIdx.x;
    int stride = gridDim.x * blockDim.x;
    for (int i = i0; i < NNc; i += stride) { g_degi[i] = 0; g_degsrc[i] = 0.f; }
    for (int i = i0; i < Bg*KCc*HIDc; i += stride) g_sx[i] = 0.f;
    for (int i = i0; i < Bg*KCc*KCc; i += stride) g_ss[i] = 0.f;
    for (int i = i0; i < Bg*KCc; i += stride) { g_ca[i] = 0.f; g_cs[i] = 0.f; }
    for (int i = i0; i < Bg*CINc; i += stride) { g_gnsum[i] = 0.f; g_gnsq[i] = 0.f; }
    if (i0 < Bg) { g_ecount[i0] = 0.f; g_trace[i0] = 0.f; }
    if (i0 == 0) g_counter = 0;
}

// ---------------- K1: edge convert (per-block int64 detect) + degree histos ----------------
__global__ __launch_bounds__(256) void k_convert_deg(const void* __restrict__ ebuf) {
    __shared__ float ec[Bg];
    __shared__ int nz;
    int t = threadIdx.x;
    if (t < Bg) ec[t] = 0.f;
    if (t == 0) nz = 0;
    __syncthreads();
    int e = blockIdx.x * 256 + t;
    // Per-block dtype detection: odd 32-bit words are int64 hi-halves (all 0)
    // or genuine node ids (~random). Consensus across blocks guaranteed.
    const int* w32 = (const int*)ebuf;
    unsigned any = __ballot_sync(0xffffffffu, w32[e * 2 + 1] != 0);
    if ((t & 31) == 0 && any) atomicOr(&nz, 1);
    __syncthreads();
    int s, d;
    if (nz == 0) {   // int64
        const long long* p = (const long long*)ebuf;
        s = (int)p[e] & (NNc - 1);
        d = (int)p[EEc + e] & (NNc - 1);
    } else {         // int32
        s = w32[e] & (NNc - 1);
        d = w32[EEc + e] & (NNc - 1);
    }
    g_src[e] = s;
    g_dst[e] = d;
    atomicAdd(&g_degi[d], 1);
    atomicAdd(&g_degsrc[s], 1.f);
    atomicAdd(&ec[s >> 11], 1.f);
    __syncthreads();
    if (t < Bg) atomicAdd(&g_ecount[t], ec[t]);
}

// ---------------- K2: single-pass scan (atomic base) + dis ----------------
// 128 blocks x 256 nodes. Non-deterministic row ordering is fine: CSR fill
// cursors are already order-free; validation is rel_err based.
__global__ __launch_bounds__(256) void k_scan() {
    __shared__ int sm[256];
    __shared__ int base;
    int t = threadIdx.x;
    int n = blockIdx.x * 256 + t;
    int d = g_degi[n];
    sm[t] = d;
    __syncthreads();
    for (int o = 1; o < 256; o <<= 1) {
        int a = (t >= o) ? sm[t - o] : 0;
        __syncthreads();
        sm[t] += a;
        __syncthreads();
    }
    if (t == 255) base = atomicAdd(&g_counter, sm[255]);
    __syncthreads();
    int excl = base + sm[t] - d;
    g_rowptr[n] = excl;
    g_cursor[n] = excl;
    g_dis[n] = rsqrtf((float)d + 1.f);
}

// ---------------- K3: scatter edge srcs into CSR slots ----------------
__global__ __launch_bounds__(256) void k_fill() {
    int e = blockIdx.x * 256 + threadIdx.x;
    int d = g_dst[e];
    int pos = atomicAdd(&g_cursor[d], 1);
    g_csrc[pos] = g_src[e];
}

// ---------------- K4: GraphNorm partial sums ----------------
__global__ __launch_bounds__(256) void k_gn_part(const float* __restrict__ x) {
    __shared__ float ssum[256], ssq[256];
    int b = blockIdx.x;
    int c = threadIdx.x & 63, r0 = threadIdx.x >> 6;
    const float* xb = x + (size_t)b * NPGc * CINc + (size_t)blockIdx.y * 128 * CINc;
    float s = 0.f, q = 0.f;
    for (int r = r0; r < 128; r += 4) {
        float v = xb[r * CINc + c];
        s += v; q += v * v;
    }
    ssum[threadIdx.x] = s; ssq[threadIdx.x] = q;
    __syncthreads();
    if (threadIdx.x < 64) {
        s = ssum[c] + ssum[c+64] + ssum[c+128] + ssum[c+192];
        q = ssq[c] + ssq[c+64] + ssq[c+128] + ssq[c+192];
        atomicAdd(&g_gnsum[b*CINc + c], s);
        atomicAdd(&g_gnsq[b*CINc + c], q);
    }
}

// ---------------- K5: GN finalize (per-block) + apply + GEMM (f32x2) ----------------
__global__ __launch_bounds__(256) void k_gemm1(const float* __restrict__ x,
                                               const float* __restrict__ gnw,
                                               const float* __restrict__ gnb,
                                               const float* __restrict__ gms,
                                               const float* __restrict__ W1) {
    __shared__ float Ws[CINc][HIDc];     // 32 KB
    __shared__ float Xs[32][CINc + 1];   // 8.1 KB
    __shared__ float sshift[CINc], sscale[CINc];
    int n0 = blockIdx.x * 32;
    int b = n0 / NPGc;
    if (threadIdx.x < CINc) {
        int c = threadIdx.x;
        float mean = g_gnsum[b*CINc + c] * (1.f / NPGc);
        float ms = gms[c];
        float var = g_gnsq[b*CINc + c] * (1.f / NPGc)
                  - 2.f * ms * mean * mean + ms * ms * mean * mean;
        sshift[c] = mean * ms;
        sscale[c] = gnw[c] * rsqrtf(var + 1e-5f);
    }
    for (int i = threadIdx.x; i < CINc * HIDc; i += 256)
        Ws[i >> 7][i & 127] = W1[i];
    __syncthreads();
    for (int i = threadIdx.x; i < 32 * CINc; i += 256) {
        int r = i >> 6, c = i & 63;
        float v = x[(size_t)(n0 + r) * CINc + c];
        Xs[r][c] = (v - sshift[c]) * sscale[c] + gnb[c];
    }
    __syncthreads();

    int q = threadIdx.x & 7;     // node quad (4 nodes)
    int jg = threadIdx.x >> 3;   // output group (4 outputs = 2 f32x2 pairs)
    unsigned long long acc2[4][2];
#pragma unroll
    for (int i = 0; i < 4; i++) { acc2[i][0] = 0ull; acc2[i][1] = 0ull; }

    for (int k = 0; k < CINc; k++) {
        unsigned long long w01 = *(const unsigned long long*)&Ws[k][jg*4];
        unsigned long long w23 = *(const unsigned long long*)&Ws[k][jg*4+2];
#pragma unroll
        for (int i = 0; i < 4; i++) {
            float a = Xs[q*4+i][k];
            unsigned long long a2 = f2pack(a, a);
            acc2[i][0] = ffma2(a2, w01, acc2[i][0]);
            acc2[i][1] = ffma2(a2, w23, acc2[i][1]);
        }
    }
#pragma unroll
    for (int i = 0; i < 4; i++) {
        float2 f01 = f2unpack(acc2[i][0]);
        float2 f23 = f2unpack(acc2[i][1]);
        g_hlin4[(size_t)(n0 + q*4 + i) * (HIDc/4) + jg] =
            make_float4(f01.x, f01.y, f23.x, f23.y);
    }
}

// ---------------- K6: CSR gather (f32x2 accumulate) ----------------
__global__ __launch_bounds__(256) void k_gather() {
    int n = (blockIdx.x * 256 + threadIdx.x) >> 5;
    int lane = threadIdx.x & 31;
    if (n >= NNc) return;
    int rs  = g_rowptr[n];
    int deg = g_degi[n];
    float disd = g_dis[n];
    unsigned long long a01 = 0ull, a23 = 0ull;
#pragma unroll 4
    for (int i = 0; i < deg; i++) {
        int s = g_csrc[rs + i];
        float c = disd * g_dis[s];
        unsigned long long c2 = f2pack(c, c);
        float4 v = g_hlin4[(size_t)s * (HIDc/4) + lane];
        a01 = ffma2(c2, f2pack(v.x, v.y), a01);
        a23 = ffma2(c2, f2pack(v.z, v.w), a23);
    }
    float2 f01 = f2unpack(a01), f23 = f2unpack(a23);
    g_hagg4[(size_t)n * (HIDc/4) + lane] = make_float4(f01.x, f01.y, f23.x, f23.y);
}

// ---------------- K7: fused finalize-h + softmax + node reductions ----------------
__global__ __launch_bounds__(256) void k_fin_red(const float* __restrict__ b1,
                                                 const float* __restrict__ Wp,
                                                 const float* __restrict__ bp,
                                                 float* __restrict__ out_s) {
    __shared__ float Wps[HIDc * KCc];  // 16 KB
    __shared__ float sH[16][HIDc];     // 8 KB
    __shared__ float sS[16][KCc];      // 2 KB
    __shared__ float sD[16];
    __shared__ float b1s[HIDc];
    __shared__ float bps[KCc];
    int tid = threadIdx.x;
    int b = blockIdx.x;
    int n0 = b * NPGc + blockIdx.y * 128;
    for (int i = tid; i < HIDc * KCc; i += 256) Wps[i] = Wp[i];
    if (tid < HIDc) b1s[tid] = b1[tid];
    if (tid < KCc)  bps[tid] = bp[tid];

    int warp = tid >> 5, lane = tid & 31;
    int k = tid >> 3, j8 = tid & 7;
    unsigned long long accx2[8];
#pragma unroll
    for (int i = 0; i < 8; i++) accx2[i] = 0ull;
    float accss[4] = {0.f, 0.f, 0.f, 0.f};
    float accca = 0.f, acccs = 0.f;

    for (int tile = 0; tile < 8; tile++) {
        int base = n0 + tile * 16;
        __syncthreads();
        for (int idx = tid; idx < 16 * HIDc; idx += 256) {
            int nl = idx >> 7, j = idx & 127;
            int n = base + nl;
            float dis = g_dis[n];
            float v = g_hagg[(size_t)n*HIDc + j]
                    + dis * dis * g_hlin[(size_t)n*HIDc + j] + b1s[j];
            sH[nl][j] = fmaxf(v, 0.f);
        }
        if (tid < 16) sD[tid] = g_degsrc[base + tid];
        __syncthreads();
#pragma unroll
        for (int u = 0; u < 2; u++) {
            int nl = warp * 2 + u;
            float acc = bps[lane];
#pragma unroll 8
            for (int j = 0; j < HIDc; j++)
                acc += sH[nl][j] * Wps[j * KCc + lane];
            float m = acc;
#pragma unroll
            for (int o = 16; o; o >>= 1) m = fmaxf(m, __shfl_xor_sync(0xffffffffu, m, o));
            float e = expf(acc - m);
            float sum = e;
#pragma unroll
            for (int o = 16; o; o >>= 1) sum += __shfl_xor_sync(0xffffffffu, sum, o);
            float sv = e / sum;
            sS[nl][lane] = sv;
            out_s[(size_t)(base + nl) * KCc + lane] = sv;
        }
        __syncthreads();
        // S^T H with paired columns: thread covers j = 2*j8 + 16*jj + {0,1}
#pragma unroll 4
        for (int nn = 0; nn < 16; nn++) {
            float sk = sS[nn][k];
            unsigned long long sk2 = f2pack(sk, sk);
            const unsigned long long* row = (const unsigned long long*)&sH[nn][0];
#pragma unroll
            for (int jj = 0; jj < 8; jj++)
                accx2[jj] = ffma2(sk2, row[j8 + jj * 8], accx2[jj]);
#pragma unroll
            for (int i = 0; i < 4; i++) {
                int idx = tid * 4 + i;
                accss[i] += sS[nn][idx >> 5] * sS[nn][idx & 31];
            }
            if (tid < 32) {
                float sv = sS[nn][tid];
                accca += sv * sD[nn];
                acccs += sv;
            }
        }
    }
#pragma unroll
    for (int jj = 0; jj < 8; jj++) {
        float2 r = f2unpack(accx2[jj]);
        atomicAdd(&g_sx[b*KCc*HIDc + k*HIDc + 2*j8 + 16*jj], r.x);
        atomicAdd(&g_sx[b*KCc*HIDc + k*HIDc + 2*j8 + 16*jj + 1], r.y);
    }
#pragma unroll
    for (int i = 0; i < 4; i++)
        atomicAdd(&g_ss[b*KCc*KCc + tid*4 + i], accss[i]);
    if (tid < 32) {
        atomicAdd(&g_ca[b*KCc + tid], accca);
        atomicAdd(&g_cs[b*KCc + tid], acccs);
    }
}

// ---------------- K8: spectral trace per graph (reads out_s) ----------------
__global__ __launch_bounds__(256) void k_trace(const float* __restrict__ s) {
    __shared__ float sacc[Bg];
    if (threadIdx.x < Bg) sacc[threadIdx.x] = 0.f;
    __syncthreads();
    int wg = (blockIdx.x * 256 + threadIdx.x) >> 5;
    int lane = threadIdx.x & 31;
    for (int t = 0; t < 16; t++) {
        int e = wg * 16 + t;
        int sn = g_src[e];
        int dn = g_dst[e];
        float p = s[(size_t)sn*KCc + lane] * s[(size_t)dn*KCc + lane];
#pragma unroll
        for (int o = 16; o; o >>= 1) p += __shfl_xor_sync(0xffffffffu, p, o);
        if (lane == 0) atomicAdd(&sacc[sn >> 11], p);
    }
    __syncthreads();
    if (threadIdx.x < Bg) atomicAdd(&g_trace[threadIdx.x], sacc[threadIdx.x]);
}

// ---------------- K9: losses ----------------
__global__ __launch_bounds__(512) void k_losses(float* __restrict__ out_loss) {
    __shared__ float bl[Bg];
    int w = threadIdx.x >> 5, lane = threadIdx.x & 31;
    if (w < Bg) {
        int b = w;
        float m = g_ecount[b] * 0.5f;
        float q = 0.f;
        for (int i = 0; i < 32; i++) {
            float v = g_ss[b*1024 + i*32 + lane];
            q += v * v;
        }
#pragma unroll
        for (int o = 16; o; o >>= 1) q += __shfl_xor_sync(0xffffffffu, q, o);
        float nrm = sqrtf(q);
        float inv_sk = rsqrtf((float)KCc);
        float oo = 0.f;
        for (int i = 0; i < 32; i++) {
            float v = g_ss[b*1024 + i*32 + lane] / nrm - ((i == lane) ? inv_sk : 0.f);
            oo += v * v;
        }
#pragma unroll
        for (int o = 16; o; o >>= 1) oo += __shfl_xor_sync(0xffffffffu, oo, o);
        float cav = g_ca[b*KCc + lane];
        float ca2 = cav * cav;
#pragma unroll
        for (int o = 16; o; o >>= 1) ca2 += __shfl_xor_sync(0xffffffffu, ca2, o);
        float csv = g_cs[b*KCc + lane];
        float cs2 = csv * csv;
#pragma unroll
        for (int o = 16; o; o >>= 1) cs2 += __shfl_xor_sync(0xffffffffu, cs2, o);
        if (lane == 0) {
            float spec = -(g_trace[b] - ca2 / (2.f * m)) / (2.f * m);
            float ortho = sqrtf(oo);
            float clus = sqrtf(cs2) / (float)NPGc * sqrtf((float)KCc) - 1.f;
            bl[b] = spec + ortho + clus;
        }
    }
    __syncthreads();
    if (threadIdx.x == 0) {
        float t = 0.f;
        for (int i = 0; i < Bg; i++) t += bl[i];
        out_loss[0] = t / (float)Bg;
    }
}

// ---------------- K10: selu + log_softmax of out_x ----------------
__global__ __launch_bounds__(128) void k_outx(float* __restrict__ out) {
    __shared__ float redm[4], reds[4];
    int row = blockIdx.x;
    int t = threadIdx.x;
    int warp = t >> 5, lane = t & 31;
    float v = g_sx[row * HIDc + t];
    const float sc = 1.0507009873554805f, al = 1.6732632423543772f;
    v = (v > 0.f) ? sc * v : sc * al * (expf(v) - 1.f);
    float mx = v;
#pragma unroll
    for (int o = 16; o; o >>= 1) mx = fmaxf(mx, __shfl_xor_sync(0xffffffffu, mx, o));
    if (lane == 0) redm[warp] = mx;
    __syncthreads();
    mx = fmaxf(fmaxf(redm[0], redm[1]), fmaxf(redm[2], redm[3]));
    float e = expf(v - mx);
    float sum = e;
#pragma unroll
    for (int o = 16; o; o >>= 1) sum += __shfl_xor_sync(0xffffffffu, sum, o);
    if (lane == 0) reds[warp] = sum;
    __syncthreads();
    sum = reds[0] + reds[1] + reds[2] + reds[3];
    out[row * HIDc + t] = v - mx - logf(sum);
}

// ---------------- launch ----------------
extern "C" void kernel_launch(void* const* d_in, const int* in_sizes, int n_in,
                              void* d_out, int out_size) {
    int i_x = 0, i_W1 = 4, i_b1 = 5, i_Wp = 6, i_bp = 7, i_ei = 8;
    for (int i = 0; i < n_in; i++) {
        int sz = in_sizes[i];
        if (sz == NNc * CINc)       i_x  = i;
        else if (sz == CINc * HIDc) i_W1 = i;
        else if (sz == HIDc)        i_b1 = i;
        else if (sz == HIDc * KCc)  i_Wp = i;
        else if (sz == KCc)         i_bp = i;
        else if (sz == 2 * EEc)     i_ei = i;
    }
    const float* x   = (const float*)d_in[i_x];
    const float* gnw = (const float*)d_in[1];
    const float* gnb = (const float*)d_in[2];
    const float* gms = (const float*)d_in[3];
    const float* W1  = (const float*)d_in[i_W1];
    const float* b1  = (const float*)d_in[i_b1];
    const float* Wp  = (const float*)d_in[i_Wp];
    const float* bp  = (const float*)d_in[i_bp];
    const void*  ei  = d_in[i_ei];

    float* out = (float*)d_out;
    float* out_loss = out + Bg*KCc*HIDc;          // 65536
    float* out_s    = out + Bg*KCc*HIDc + 1;      // 65537

    k_zero<<<1024, 256>>>();
    k_convert_deg<<<EEc/256, 256>>>(ei);
    k_scan<<<NNc/256, 256>>>();
    k_fill<<<EEc/256, 256>>>();
    k_gn_part<<<dim3(Bg, 16), 256>>>(x);
    k_gemm1<<<NNc/32, 256>>>(x, gnw, gnb, gms, W1);
    k_gather<<<NNc/8, 256>>>();
    k_fin_red<<<dim3(Bg, 16), 256>>>(b1, Wp, bp, out_s);
    k_trace<<<EEc/16/8, 256>>>(out_s);
    k_losses<<<1, 512>>>(out_loss);
    k_outx<<<Bg*KCc, 128>>>(out);
}

// round 11
// speedup vs baseline: 1.3619x; 1.0239x over previous
#include <cuda_runtime.h>

// Problem constants
#define Bg    16
#define NPGc  2048
#define NNc   32768      // Bg * NPGc
#define CINc  64
#define HIDc  128
#define KCc   32
#define EEc   524288

// ---------------- device scratch ----------------
__device__ float4 g_hlin4[NNc*HIDc/4];    // xn @ W1 (pre-aggregation)
__device__ float4 g_hagg4[NNc*HIDc/4];    // aggregated neighbor sums
#define g_hlin ((float*)g_hlin4)
#define g_hagg ((float*)g_hagg4)

__device__ int   g_src[EEc];
__device__ int   g_dst[EEc];
__device__ int   g_csrc[EEc];             // CSR column (src) indices, grouped by dst
__device__ int   g_degi[NNc];             // in-degree (int)
__device__ int   g_rowptr[NNc];           // CSR row starts
__device__ int   g_cursor[NNc];           // fill cursors
__device__ int   g_counter;               // scan base allocator

__device__ float g_gnsum[Bg*CINc];
__device__ float g_gnsq[Bg*CINc];
__device__ float g_dis[NNc];              // rsqrt(in_deg + 1)
__device__ float g_degsrc[NNc];           // DMoN degrees (out-degree)
__device__ float g_ecount[Bg];
__device__ float g_trace[Bg];             // sum_e dot(s_src, s_dst)
__device__ float g_sx[Bg*KCc*HIDc];       // S^T X per graph
__device__ float g_ss[Bg*KCc*KCc];        // S^T S per graph
__device__ float g_ca[Bg*KCc];            // S^T degrees
__device__ float g_cs[Bg*KCc];            // cluster sizes

// ---------------- f32x2 helpers ----------------
__device__ __forceinline__ unsigned long long f2pack(float x, float y) {
    unsigned long long r;
    asm("mov.b64 %0, {%1, %2};" : "=l"(r) : "f"(x), "f"(y));
    return r;
}
__device__ __forceinline__ unsigned long long ffma2(unsigned long long a,
                                                    unsigned long long b,
                                                    unsigned long long c) {
    unsigned long long d;
    asm("fma.rn.f32x2 %0, %1, %2, %3;" : "=l"(d) : "l"(a), "l"(b), "l"(c));
    return d;
}
__device__ __forceinline__ float2 f2unpack(unsigned long long v) {
    float2 f;
    asm("mov.b64 {%0, %1}, %2;" : "=f"(f.x), "=f"(f.y) : "l"(v));
    return f;
}

// ---------------- K0: zero small accumulators ----------------
__global__ __launch_bounds__(256) void k_zero() {
    int i0 = blockIdx.x * blockDim.x + threadIdx.x;
    int stride = gridDim.x * blockDim.x;
    for (int i = i0; i < NNc; i += stride) { g_degi[i] = 0; g_degsrc[i] = 0.f; }
    for (int i = i0; i < Bg*KCc*HIDc; i += stride) g_sx[i] = 0.f;
    for (int i = i0; i < Bg*KCc*KCc; i += stride) g_ss[i] = 0.f;
    for (int i = i0; i < Bg*KCc; i += stride) { g_ca[i] = 0.f; g_cs[i] = 0.f; }
    for (int i = i0; i < Bg*CINc; i += stride) { g_gnsum[i] = 0.f; g_gnsq[i] = 0.f; }
    if (i0 < Bg) { g_ecount[i0] = 0.f; g_trace[i0] = 0.f; }
    if (i0 == 0) g_counter = 0;
}

// ---------------- K1: edge convert (per-block int64 detect) + degree histos ----------------
__global__ __launch_bounds__(256) void k_convert_deg(const void* __restrict__ ebuf) {
    __shared__ int nz;
    int t = threadIdx.x;
    if (t == 0) nz = 0;
    __syncthreads();
    int e = blockIdx.x * 256 + t;
    const int* w32 = (const int*)ebuf;
    unsigned any = __ballot_sync(0xffffffffu, w32[e * 2 + 1] != 0);
    if ((t & 31) == 0 && any) atomicOr(&nz, 1);
    __syncthreads();
    int s, d;
    if (nz == 0) {   // int64
        const long long* p = (const long long*)ebuf;
        s = (int)p[e] & (NNc - 1);
        d = (int)p[EEc + e] & (NNc - 1);
    } else {         // int32
        s = w32[e] & (NNc - 1);
        d = w32[EEc + e] & (NNc - 1);
    }
    g_src[e] = s;
    g_dst[e] = d;
    atomicAdd(&g_degi[d], 1);
    atomicAdd(&g_degsrc[s], 1.f);
}

// ---------------- K2: single-pass scan (atomic base) + dis ----------------
__global__ __launch_bounds__(256) void k_scan() {
    __shared__ int sm[256];
    __shared__ int base;
    int t = threadIdx.x;
    int n = blockIdx.x * 256 + t;
    int d = g_degi[n];
    sm[t] = d;
    __syncthreads();
    for (int o = 1; o < 256; o <<= 1) {
        int a = (t >= o) ? sm[t - o] : 0;
        __syncthreads();
        sm[t] += a;
        __syncthreads();
    }
    if (t == 255) base = atomicAdd(&g_counter, sm[255]);
    __syncthreads();
    int excl = base + sm[t] - d;
    g_rowptr[n] = excl;
    g_cursor[n] = excl;
    g_dis[n] = rsqrtf((float)d + 1.f);
}

// ---------------- K3: scatter edge srcs into CSR slots (ILP 4) ----------------
__global__ __launch_bounds__(256) void k_fill() {
    int t = blockIdx.x * 256 + threadIdx.x;   // grid 512 -> 4 edges/thread
#pragma unroll
    for (int u = 0; u < 4; u++) {
        int e = t + u * (EEc / 4);
        int d = g_dst[e];
        int pos = atomicAdd(&g_cursor[d], 1);
        g_csrc[pos] = g_src[e];
    }
}

// ---------------- K4: GraphNorm partial sums ----------------
__global__ __launch_bounds__(256) void k_gn_part(const float* __restrict__ x) {
    __shared__ float ssum[256], ssq[256];
    int b = blockIdx.x;
    int c = threadIdx.x & 63, r0 = threadIdx.x >> 6;
    const float* xb = x + (size_t)b * NPGc * CINc + (size_t)blockIdx.y * 128 * CINc;
    float s = 0.f, q = 0.f;
    for (int r = r0; r < 128; r += 4) {
        float v = xb[r * CINc + c];
        s += v; q += v * v;
    }
    ssum[threadIdx.x] = s; ssq[threadIdx.x] = q;
    __syncthreads();
    if (threadIdx.x < 64) {
        s = ssum[c] + ssum[c+64] + ssum[c+128] + ssum[c+192];
        q = ssq[c] + ssq[c+64] + ssq[c+128] + ssq[c+192];
        atomicAdd(&g_gnsum[b*CINc + c], s);
        atomicAdd(&g_gnsq[b*CINc + c], q);
    }
}

// ---------------- K5: GN finalize (per-block) + apply + GEMM (f32x2) ----------------
__global__ __launch_bounds__(256) void k_gemm1(const float* __restrict__ x,
                                               const float* __restrict__ gnw,
                                               const float* __restrict__ gnb,
                                               const float* __restrict__ gms,
                                               const float* __restrict__ W1) {
    __shared__ float Ws[CINc][HIDc];     // 32 KB
    __shared__ float Xs[32][CINc + 1];   // 8.1 KB
    __shared__ float sshift[CINc], sscale[CINc];
    int n0 = blockIdx.x * 32;
    int b = n0 / NPGc;
    if (threadIdx.x < CINc) {
        int c = threadIdx.x;
        float mean = g_gnsum[b*CINc + c] * (1.f / NPGc);
        float ms = gms[c];
        float var = g_gnsq[b*CINc + c] * (1.f / NPGc)
                  - 2.f * ms * mean * mean + ms * ms * mean * mean;
        sshift[c] = mean * ms;
        sscale[c] = gnw[c] * rsqrtf(var + 1e-5f);
    }
    for (int i = threadIdx.x; i < CINc * HIDc; i += 256)
        Ws[i >> 7][i & 127] = W1[i];
    __syncthreads();
    for (int i = threadIdx.x; i < 32 * CINc; i += 256) {
        int r = i >> 6, c = i & 63;
        float v = x[(size_t)(n0 + r) * CINc + c];
        Xs[r][c] = (v - sshift[c]) * sscale[c] + gnb[c];
    }
    __syncthreads();

    int q = threadIdx.x & 7;
    int jg = threadIdx.x >> 3;
    unsigned long long acc2[4][2];
#pragma unroll
    for (int i = 0; i < 4; i++) { acc2[i][0] = 0ull; acc2[i][1] = 0ull; }

    for (int k = 0; k < CINc; k++) {
        unsigned long long w01 = *(const unsigned long long*)&Ws[k][jg*4];
        unsigned long long w23 = *(const unsigned long long*)&Ws[k][jg*4+2];
#pragma unroll
        for (int i = 0; i < 4; i++) {
            float a = Xs[q*4+i][k];
            unsigned long long a2 = f2pack(a, a);
            acc2[i][0] = ffma2(a2, w01, acc2[i][0]);
            acc2[i][1] = ffma2(a2, w23, acc2[i][1]);
        }
    }
#pragma unroll
    for (int i = 0; i < 4; i++) {
        float2 f01 = f2unpack(acc2[i][0]);
        float2 f23 = f2unpack(acc2[i][1]);
        g_hlin4[(size_t)(n0 + q*4 + i) * (HIDc/4) + jg] =
            make_float4(f01.x, f01.y, f23.x, f23.y);
    }
}

// ---------------- K6: CSR gather with shuffled index prefetch ----------------
__global__ __launch_bounds__(256) void k_gather() {
    int n = (blockIdx.x * 256 + threadIdx.x) >> 5;
    int lane = threadIdx.x & 31;
    if (n >= NNc) return;
    int rs  = g_rowptr[n];
    int deg = g_degi[n];
    float disd = g_dis[n];
    unsigned long long a01 = 0ull, a23 = 0ull;
    for (int base = 0; base < deg; base += 32) {
        int l = base + lane;
        int idx = 0; float cl = 0.f;
        if (l < deg) {
            idx = g_csrc[rs + l];
            cl = disd * g_dis[idx];
        }
        int cnt = min(32, deg - base);
#pragma unroll 4
        for (int i = 0; i < cnt; i++) {
            int s  = __shfl_sync(0xffffffffu, idx, i);
            float c = __shfl_sync(0xffffffffu, cl, i);
            float4 v = g_hlin4[(size_t)s * (HIDc/4) + lane];
            unsigned long long c2 = f2pack(c, c);
            a01 = ffma2(c2, f2pack(v.x, v.y), a01);
            a23 = ffma2(c2, f2pack(v.z, v.w), a23);
        }
    }
    float2 f01 = f2unpack(a01), f23 = f2unpack(a23);
    g_hagg4[(size_t)n * (HIDc/4) + lane] = make_float4(f01.x, f01.y, f23.x, f23.y);
}

// ---------------- K7: fused finalize-h + softmax + node reductions ----------------
__global__ __launch_bounds__(256) void k_fin_red(const float* __restrict__ b1,
                                                 const float* __restrict__ Wp,
                                                 const float* __restrict__ bp,
                                                 float* __restrict__ out_s) {
    __shared__ float Wps[HIDc * KCc];  // 16 KB
    __shared__ float sH[16][HIDc];     // 8 KB
    __shared__ float sS[16][KCc];      // 2 KB
    __shared__ float sD[16];
    __shared__ float b1s[HIDc];
    __shared__ float bps[KCc];
    int tid = threadIdx.x;
    int b = blockIdx.x;
    int n0 = b * NPGc + blockIdx.y * 128;
    for (int i = tid; i < HIDc * KCc; i += 256) Wps[i] = Wp[i];
    if (tid < HIDc) b1s[tid] = b1[tid];
    if (tid < KCc)  bps[tid] = bp[tid];

    int warp = tid >> 5, lane = tid & 31;
    int k = tid >> 3, j8 = tid & 7;
    unsigned long long accx2[8];
#pragma unroll
    for (int i = 0; i < 8; i++) accx2[i] = 0ull;
    float accss[4] = {0.f, 0.f, 0.f, 0.f};
    float accca = 0.f, acccs = 0.f, eacc = 0.f;

    for (int tile = 0; tile < 8; tile++) {
        int base = n0 + tile * 16;
        __syncthreads();
        for (int idx = tid; idx < 16 * HIDc; idx += 256) {
            int nl = idx >> 7, j = idx & 127;
            int n = base + nl;
            float dis = g_dis[n];
            float v = g_hagg[(size_t)n*HIDc + j]
                    + dis * dis * g_hlin[(size_t)n*HIDc + j] + b1s[j];
            sH[nl][j] = fmaxf(v, 0.f);
        }
        if (tid < 16) sD[tid] = g_degsrc[base + tid];
        __syncthreads();
#pragma unroll
        for (int u = 0; u < 2; u++) {
            int nl = warp * 2 + u;
            float acc = bps[lane];
#pragma unroll 8
            for (int j = 0; j < HIDc; j++)
                acc += sH[nl][j] * Wps[j * KCc + lane];
            float m = acc;
#pragma unroll
            for (int o = 16; o; o >>= 1) m = fmaxf(m, __shfl_xor_sync(0xffffffffu, m, o));
            float e = expf(acc - m);
            float sum = e;
#pragma unroll
            for (int o = 16; o; o >>= 1) sum += __shfl_xor_sync(0xffffffffu, sum, o);
            float sv = e / sum;
            sS[nl][lane] = sv;
            out_s[(size_t)(base + nl) * KCc + lane] = sv;
        }
        __syncthreads();
        if (tid < 16) eacc += sD[tid];
#pragma unroll 4
        for (int nn = 0; nn < 16; nn++) {
            float sk = sS[nn][k];
            unsigned long long sk2 = f2pack(sk, sk);
            const unsigned long long* row = (const unsigned long long*)&sH[nn][0];
#pragma unroll
            for (int jj = 0; jj < 8; jj++)
                accx2[jj] = ffma2(sk2, row[j8 + jj * 8], accx2[jj]);
#pragma unroll
            for (int i = 0; i < 4; i++) {
                int idx = tid * 4 + i;
                accss[i] += sS[nn][idx >> 5] * sS[nn][idx & 31];
            }
            if (tid < 32) {
                float sv = sS[nn][tid];
                accca += sv * sD[nn];
                acccs += sv;
            }
        }
    }
#pragma unroll
    for (int jj = 0; jj < 8; jj++) {
        float2 r = f2unpack(accx2[jj]);
        atomicAdd(&g_sx[b*KCc*HIDc + k*HIDc + 2*j8 + 16*jj], r.x);
        atomicAdd(&g_sx[b*KCc*HIDc + k*HIDc + 2*j8 + 16*jj + 1], r.y);
    }
#pragma unroll
    for (int i = 0; i < 4; i++)
        atomicAdd(&g_ss[b*KCc*KCc + tid*4 + i], accss[i]);
    if (tid < 32) {
        atomicAdd(&g_ca[b*KCc + tid], accca);
        atomicAdd(&g_cs[b*KCc + tid], acccs);
    }
    if (tid < 16) atomicAdd(&g_ecount[b], eacc);
}

// ---------------- K8: spectral trace via CSR ----------------
// One warp per node; 8 nodes per block (grid NNc/8). All 8 nodes share a graph
// since NPGc % 8 == 0.
__global__ __launch_bounds__(256) void k_trace(const float* __restrict__ s) {
    __shared__ float sacc;
    if (threadIdx.x == 0) sacc = 0.f;
    __syncthreads();
    int n = (blockIdx.x * 256 + threadIdx.x) >> 5;   // global warp id = node id
    int lane = threadIdx.x & 31;
    int rs  = g_rowptr[n];
    int deg = g_degi[n];
    float accv = 0.f;
    for (int base = 0; base < deg; base += 32) {
        int l = base + lane;
        int idx = (l < deg) ? g_csrc[rs + l] : 0;
        int cnt = min(32, deg - base);
#pragma unroll 4
        for (int i = 0; i < cnt; i++) {
            int sn = __shfl_sync(0xffffffffu, idx, i);
            accv += s[(size_t)sn * KCc + lane];
        }
    }
    float p = accv * s[(size_t)n * KCc + lane];
#pragma unroll
    for (int o = 16; o; o >>= 1) p += __shfl_xor_sync(0xffffffffu, p, o);
    if (lane == 0) atomicAdd(&sacc, p);
    __syncthreads();
    if (threadIdx.x == 0) atomicAdd(&g_trace[(blockIdx.x * 8) >> 11], sacc);
}

// ---------------- K9: losses ----------------
__global__ __launch_bounds__(512) void k_losses(float* __restrict__ out_loss) {
    __shared__ float bl[Bg];
    int w = threadIdx.x >> 5, lane = threadIdx.x & 31;
    if (w < Bg) {
        int b = w;
        float m = g_ecount[b] * 0.5f;
        float q = 0.f;
        for (int i = 0; i < 32; i++) {
            float v = g_ss[b*1024 + i*32 + lane];
            q += v * v;
        }
#pragma unroll
        for (int o = 16; o; o >>= 1) q += __shfl_xor_sync(0xffffffffu, q, o);
        float nrm = sqrtf(q);
        float inv_sk = rsqrtf((float)KCc);
        float oo = 0.f;
        for (int i = 0; i < 32; i++) {
            float v = g_ss[b*1024 + i*32 + lane] / nrm - ((i == lane) ? inv_sk : 0.f);
            oo += v * v;
        }
#pragma unroll
        for (int o = 16; o; o >>= 1) oo += __shfl_xor_sync(0xffffffffu, oo, o);
        float cav = g_ca[b*KCc + lane];
        float ca2 = cav * cav;
#pragma unroll
        for (int o = 16; o; o >>= 1) ca2 += __shfl_xor_sync(0xffffffffu, ca2, o);
        float csv = g_cs[b*KCc + lane];
        float cs2 = csv * csv;
#pragma unroll
        for (int o = 16; o; o >>= 1) cs2 += __shfl_xor_sync(0xffffffffu, cs2, o);
        if (lane == 0) {
            float spec = -(g_trace[b] - ca2 / (2.f * m)) / (2.f * m);
            float ortho = sqrtf(oo);
            float clus = sqrtf(cs2) / (float)NPGc * sqrtf((float)KCc) - 1.f;
            bl[b] = spec + ortho + clus;
        }
    }
    __syncthreads();
    if (threadIdx.x == 0) {
        float t = 0.f;
        for (int i = 0; i < Bg; i++) t += bl[i];
        out_loss[0] = t / (float)Bg;
    }
}

// ---------------- K10: selu + log_softmax of out_x ----------------
__global__ __launch_bounds__(128) void k_outx(float* __restrict__ out) {
    __shared__ float redm[4], reds[4];
    int row = blockIdx.x;
    int t = threadIdx.x;
    int warp = t >> 5, lane = t & 31;
    float v = g_sx[row * HIDc + t];
    const float sc = 1.0507009873554805f, al = 1.6732632423543772f;
    v = (v > 0.f) ? sc * v : sc * al * (expf(v) - 1.f);
    float mx = v;
#pragma unroll
    for (int o = 16; o; o >>= 1) mx = fmaxf(mx, __shfl_xor_sync(0xffffffffu, mx, o));
    if (lane == 0) redm[warp] = mx;
    __syncthreads();
    mx = fmaxf(fmaxf(redm[0], redm[1]), fmaxf(redm[2], redm[3]));
    float e = expf(v - mx);
    float sum = e;
#pragma unroll
    for (int o = 16; o; o >>= 1) sum += __shfl_xor_sync(0xffffffffu, sum, o);
    if (lane == 0) reds[warp] = sum;
    __syncthreads();
    sum = reds[0] + reds[1] + reds[2] + reds[3];
    out[row * HIDc + t] = v - mx - logf(sum);
}

// ---------------- launch ----------------
extern "C" void kernel_launch(void* const* d_in, const int* in_sizes, int n_in,
                              void* d_out, int out_size) {
    int i_x = 0, i_W1 = 4, i_b1 = 5, i_Wp = 6, i_bp = 7, i_ei = 8;
    for (int i = 0; i < n_in; i++) {
        int sz = in_sizes[i];
        if (sz == NNc * CINc)       i_x  = i;
        else if (sz == CINc * HIDc) i_W1 = i;
        else if (sz == HIDc)        i_b1 = i;
        else if (sz == HIDc * KCc)  i_Wp = i;
        else if (sz == KCc)         i_bp = i;
        else if (sz == 2 * EEc)     i_ei = i;
    }
    const float* x   = (const float*)d_in[i_x];
    const float* gnw = (const float*)d_in[1];
    const float* gnb = (const float*)d_in[2];
    const float* gms = (const float*)d_in[3];
    const float* W1  = (const float*)d_in[i_W1];
    const float* b1  = (const float*)d_in[i_b1];
    const float* Wp  = (const float*)d_in[i_Wp];
    const float* bp  = (const float*)d_in[i_bp];
    const void*  ei  = d_in[i_ei];

    float* out = (float*)d_out;
    float* out_loss = out + Bg*KCc*HIDc;          // 65536
    float* out_s    = out + Bg*KCc*HIDc + 1;      // 65537

    k_zero<<<1024, 256>>>();
    k_convert_deg<<<EEc/256, 256>>>(ei);
    k_scan<<<NNc/256, 256>>>();
    k_fill<<<512, 256>>>();
    k_gn_part<<<dim3(Bg, 16), 256>>>(x);
    k_gemm1<<<NNc/32, 256>>>(x, gnw, gnb, gms, W1);
    k_gather<<<NNc/8, 256>>>();
    k_fin_red<<<dim3(Bg, 16), 256>>>(b1, Wp, bp, out_s);
    k_trace<<<NNc/8, 256>>>(out_s);
    k_losses<<<1, 512>>>(out_loss);
    k_outx<<<Bg*KCc, 128>>>(out);
}

// round 13
// speedup vs baseline: 1.3783x; 1.0121x over previous
#include <cuda_runtime.h>

// Problem constants
#define Bg    16
#define NPGc  2048
#define NNc   32768      // Bg * NPGc
#define CINc  64
#define HIDc  128
#define KCc   32
#define EEc   524288

// ---------------- device scratch ----------------
__device__ float4 g_hlin4[NNc*HIDc/4];    // xn @ W1 (pre-aggregation)
__device__ float4 g_hagg4[NNc*HIDc/4];    // aggregated neighbor sums
#define g_hlin ((float*)g_hlin4)
#define g_hagg ((float*)g_hagg4)

__device__ int   g_src[EEc];
__device__ int   g_dst[EEc];
__device__ int   g_rank[EEc];             // rank of edge within its dst bucket
__device__ int   g_csrc[EEc];             // CSR column (src) indices, grouped by dst
__device__ int   g_degi[NNc];             // in-degree (int)
__device__ int   g_rowptr[NNc];           // CSR row starts
__device__ int   g_counter;               // scan base allocator

__device__ float g_gnsum[Bg*CINc];
__device__ float g_gnsq[Bg*CINc];
__device__ float g_dis[NNc];              // rsqrt(in_deg + 1)
__device__ float g_degsrc[NNc];           // DMoN degrees (out-degree)
__device__ float g_ecount[Bg];
__device__ float g_trace[Bg];             // sum_e dot(s_src, s_dst)
__device__ float g_sx[Bg*KCc*HIDc];       // S^T X per graph
__device__ float g_ss[Bg*KCc*KCc];        // S^T S per graph
__device__ float g_ca[Bg*KCc];            // S^T degrees
__device__ float g_cs[Bg*KCc];            // cluster sizes

// ---------------- f32x2 helpers ----------------
__device__ __forceinline__ unsigned long long f2pack(float x, float y) {
    unsigned long long r;
    asm("mov.b64 %0, {%1, %2};" : "=l"(r) : "f"(x), "f"(y));
    return r;
}
__device__ __forceinline__ unsigned long long ffma2(unsigned long long a,
                                                    unsigned long long b,
                                                    unsigned long long c) {
    unsigned long long d;
    asm("fma.rn.f32x2 %0, %1, %2, %3;" : "=l"(d) : "l"(a), "l"(b), "l"(c));
    return d;
}
__device__ __forceinline__ float2 f2unpack(unsigned long long v) {
    float2 f;
    asm("mov.b64 {%0, %1}, %2;" : "=f"(f.x), "=f"(f.y) : "l"(v));
    return f;
}

// ---------------- K0: zero small accumulators ----------------
__global__ __launch_bounds__(256) void k_zero() {
    int i0 = blockIdx.x * blockDim.x + threadIdx.x;
    int stride = gridDim.x * blockDim.x;
    for (int i = i0; i < NNc; i += stride) { g_degi[i] = 0; g_degsrc[i] = 0.f; }
    for (int i = i0; i < Bg*KCc*HIDc; i += stride) g_sx[i] = 0.f;
    for (int i = i0; i < Bg*KCc*KCc; i += stride) g_ss[i] = 0.f;
    for (int i = i0; i < Bg*KCc; i += stride) { g_ca[i] = 0.f; g_cs[i] = 0.f; }
    for (int i = i0; i < Bg*CINc; i += stride) { g_gnsum[i] = 0.f; g_gnsq[i] = 0.f; }
    if (i0 < Bg) { g_ecount[i0] = 0.f; g_trace[i0] = 0.f; }
    if (i0 == 0) g_counter = 0;
}

// ---------------- K1: edge convert + degree histos + in-bucket rank ----------------
// atomicAdd's return value IS the rank of this edge within its dst bucket.
__global__ __launch_bounds__(256) void k_convert_deg(const void* __restrict__ ebuf) {
    __shared__ int nz;
    int t = threadIdx.x;
    if (t == 0) nz = 0;
    __syncthreads();
    int e = blockIdx.x * 256 + t;
    const int* w32 = (const int*)ebuf;
    unsigned any = __ballot_sync(0xffffffffu, w32[e * 2 + 1] != 0);
    if ((t & 31) == 0 && any) atomicOr(&nz, 1);
    __syncthreads();
    int s, d;
    if (nz == 0) {   // int64
        const long long* p = (const long long*)ebuf;
        s = (int)p[e] & (NNc - 1);
        d = (int)p[EEc + e] & (NNc - 1);
    } else {         // int32
        s = w32[e] & (NNc - 1);
        d = w32[EEc + e] & (NNc - 1);
    }
    g_src[e] = s;
    g_dst[e] = d;
    g_rank[e] = atomicAdd(&g_degi[d], 1);
    atomicAdd(&g_degsrc[s], 1.f);
}

// ---------------- K2: single-pass scan (atomic base) + dis ----------------
__global__ __launch_bounds__(256) void k_scan() {
    __shared__ int sm[256];
    __shared__ int base;
    int t = threadIdx.x;
    int n = blockIdx.x * 256 + t;
    int d = g_degi[n];
    sm[t] = d;
    __syncthreads();
    for (int o = 1; o < 256; o <<= 1) {
        int a = (t >= o) ? sm[t - o] : 0;
        __syncthreads();
        sm[t] += a;
        __syncthreads();
    }
    if (t == 255) base = atomicAdd(&g_counter, sm[255]);
    __syncthreads();
    g_rowptr[n] = base + sm[t] - d;
    g_dis[n] = rsqrtf((float)d + 1.f);
}

// ---------------- K3: atomic-free CSR fill ----------------
__global__ __launch_bounds__(256) void k_fill() {
    int e = blockIdx.x * 256 + threadIdx.x;   // grid 2048
    int d = g_dst[e];
    g_csrc[g_rowptr[d] + g_rank[e]] = g_src[e];
}

// ---------------- K4: GraphNorm partial sums ----------------
__global__ __launch_bounds__(256) void k_gn_part(const float* __restrict__ x) {
    __shared__ float ssum[256], ssq[256];
    int b = blockIdx.x;
    int c = threadIdx.x & 63, r0 = threadIdx.x >> 6;
    const float* xb = x + (size_t)b * NPGc * CINc + (size_t)blockIdx.y * 128 * CINc;
    float s = 0.f, q = 0.f;
    for (int r = r0; r < 128; r += 4) {
        float v = xb[r * CINc + c];
        s += v; q += v * v;
    }
    ssum[threadIdx.x] = s; ssq[threadIdx.x] = q;
    __syncthreads();
    if (threadIdx.x < 64) {
        s = ssum[c] + ssum[c+64] + ssum[c+128] + ssum[c+192];
        q = ssq[c] + ssq[c+64] + ssq[c+128] + ssq[c+192];
        atomicAdd(&g_gnsum[b*CINc + c], s);
        atomicAdd(&g_gnsq[b*CINc + c], q);
    }
}

// ---------------- K5: GN finalize (per-block) + apply + GEMM (f32x2, 32-node tiles) ----------------
__global__ __launch_bounds__(256) void k_gemm1(const float* __restrict__ x,
                                               const float* __restrict__ gnw,
                                               const float* __restrict__ gnb,
                                               const float* __restrict__ gms,
                                               const float* __restrict__ W1) {
    __shared__ float Ws[CINc][HIDc];     // 32 KB
    __shared__ float Xs[32][CINc + 1];   // 8.1 KB
    __shared__ float sshift[CINc], sscale[CINc];
    int n0 = blockIdx.x * 32;
    int b = n0 / NPGc;
    if (threadIdx.x < CINc) {
        int c = threadIdx.x;
        float mean = g_gnsum[b*CINc + c] * (1.f / NPGc);
        float ms = gms[c];
        float var = g_gnsq[b*CINc + c] * (1.f / NPGc)
                  - 2.f * ms * mean * mean + ms * ms * mean * mean;
        sshift[c] = mean * ms;
        sscale[c] = gnw[c] * rsqrtf(var + 1e-5f);
    }
    for (int i = threadIdx.x; i < CINc * HIDc; i += 256)
        Ws[i >> 7][i & 127] = W1[i];
    __syncthreads();
    for (int i = threadIdx.x; i < 32 * CINc; i += 256) {
        int r = i >> 6, c = i & 63;
        float v = x[(size_t)(n0 + r) * CINc + c];
        Xs[r][c] = (v - sshift[c]) * sscale[c] + gnb[c];
    }
    __syncthreads();

    int q = threadIdx.x & 7;
    int jg = threadIdx.x >> 3;
    unsigned long long acc2[4][2];
#pragma unroll
    for (int i = 0; i < 4; i++) { acc2[i][0] = 0ull; acc2[i][1] = 0ull; }

    for (int k = 0; k < CINc; k++) {
        unsigned long long w01 = *(const unsigned long long*)&Ws[k][jg*4];
        unsigned long long w23 = *(const unsigned long long*)&Ws[k][jg*4+2];
#pragma unroll
        for (int i = 0; i < 4; i++) {
            float a = Xs[q*4+i][k];
            unsigned long long a2 = f2pack(a, a);
            acc2[i][0] = ffma2(a2, w01, acc2[i][0]);
            acc2[i][1] = ffma2(a2, w23, acc2[i][1]);
        }
    }
#pragma unroll
    for (int i = 0; i < 4; i++) {
        float2 f01 = f2unpack(acc2[i][0]);
        float2 f23 = f2unpack(acc2[i][1]);
        g_hlin4[(size_t)(n0 + q*4 + i) * (HIDc/4) + jg] =
            make_float4(f01.x, f01.y, f23.x, f23.y);
    }
}

// ---------------- K6: CSR gather with shuffled index prefetch ----------------
__global__ __launch_bounds__(256) void k_gather() {
    int n = (blockIdx.x * 256 + threadIdx.x) >> 5;
    int lane = threadIdx.x & 31;
    if (n >= NNc) return;
    int rs  = g_rowptr[n];
    int deg = g_degi[n];
    float disd = g_dis[n];
    unsigned long long a01 = 0ull, a23 = 0ull;
    for (int base = 0; base < deg; base += 32) {
        int l = base + lane;
        int idx = 0; float cl = 0.f;
        if (l < deg) {
            idx = g_csrc[rs + l];
            cl = disd * g_dis[idx];
        }
        int cnt = min(32, deg - base);
#pragma unroll 4
        for (int i = 0; i < cnt; i++) {
            int s  = __shfl_sync(0xffffffffu, idx, i);
            float c = __shfl_sync(0xffffffffu, cl, i);
            float4 v = g_hlin4[(size_t)s * (HIDc/4) + lane];
            unsigned long long c2 = f2pack(c, c);
            a01 = ffma2(c2, f2pack(v.x, v.y), a01);
            a23 = ffma2(c2, f2pack(v.z, v.w), a23);
        }
    }
    float2 f01 = f2unpack(a01), f23 = f2unpack(a23);
    g_hagg4[(size_t)n * (HIDc/4) + lane] = make_float4(f01.x, f01.y, f23.x, f23.y);
}

// ---------------- K7: fused finalize-h + softmax + node reductions ----------------
__global__ __launch_bounds__(256) void k_fin_red(const float* __restrict__ b1,
                                                 const float* __restrict__ Wp,
                                                 const float* __restrict__ bp,
                                                 float* __restrict__ out_s) {
    __shared__ float Wps[HIDc * KCc];  // 16 KB
    __shared__ float sH[16][HIDc];     // 8 KB
    __shared__ float sS[16][KCc];      // 2 KB
    __shared__ float sD[16];
    __shared__ float b1s[HIDc];
    __shared__ float bps[KCc];
    int tid = threadIdx.x;
    int b = blockIdx.x;
    int n0 = b * NPGc + blockIdx.y * 128;
    for (int i = tid; i < HIDc * KCc; i += 256) Wps[i] = Wp[i];
    if (tid < HIDc) b1s[tid] = b1[tid];
    if (tid < KCc)  bps[tid] = bp[tid];

    int warp = tid >> 5, lane = tid & 31;
    int k = tid >> 3, j8 = tid & 7;
    unsigned long long accx2[8];
#pragma unroll
    for (int i = 0; i < 8; i++) accx2[i] = 0ull;
    float accss[4] = {0.f, 0.f, 0.f, 0.f};
    float accca = 0.f, acccs = 0.f, eacc = 0.f;

    for (int tile = 0; tile < 8; tile++) {
        int base = n0 + tile * 16;
        __syncthreads();
        for (int idx = tid; idx < 16 * HIDc; idx += 256) {
            int nl = idx >> 7, j = idx & 127;
            int n = base + nl;
            float dis = g_dis[n];
            float v = g_hagg[(size_t)n*HIDc + j]
                    + dis * dis * g_hlin[(size_t)n*HIDc + j] + b1s[j];
            sH[nl][j] = fmaxf(v, 0.f);
        }
        if (tid < 16) sD[tid] = g_degsrc[base + tid];
        __syncthreads();
#pragma unroll
        for (int u = 0; u < 2; u++) {
            int nl = warp * 2 + u;
            float acc = bps[lane];
#pragma unroll 8
            for (int j = 0; j < HIDc; j++)
                acc += sH[nl][j] * Wps[j * KCc + lane];
            float m = acc;
#pragma unroll
            for (int o = 16; o; o >>= 1) m = fmaxf(m, __shfl_xor_sync(0xffffffffu, m, o));
            float e = expf(acc - m);
            float sum = e;
#pragma unroll
            for (int o = 16; o; o >>= 1) sum += __shfl_xor_sync(0xffffffffu, sum, o);
            float sv = e / sum;
            sS[nl][lane] = sv;
            out_s[(size_t)(base + nl) * KCc + lane] = sv;
        }
        __syncthreads();
        if (tid < 16) eacc += sD[tid];
#pragma unroll 4
        for (int nn = 0; nn < 16; nn++) {
            float sk = sS[nn][k];
            unsigned long long sk2 = f2pack(sk, sk);
            const unsigned long long* row = (const unsigned long long*)&sH[nn][0];
#pragma unroll
            for (int jj = 0; jj < 8; jj++)
                accx2[jj] = ffma2(sk2, row[j8 + jj * 8], accx2[jj]);
#pragma unroll
            for (int i = 0; i < 4; i++) {
                int idx = tid * 4 + i;
                accss[i] += sS[nn][idx >> 5] * sS[nn][idx & 31];
            }
            if (tid < 32) {
                float sv = sS[nn][tid];
                accca += sv * sD[nn];
                acccs += sv;
            }
        }
    }
#pragma unroll
    for (int jj = 0; jj < 8; jj++) {
        float2 r = f2unpack(accx2[jj]);
        atomicAdd(&g_sx[b*KCc*HIDc + k*HIDc + 2*j8 + 16*jj], r.x);
        atomicAdd(&g_sx[b*KCc*HIDc + k*HIDc + 2*j8 + 16*jj + 1], r.y);
    }
#pragma unroll
    for (int i = 0; i < 4; i++)
        atomicAdd(&g_ss[b*KCc*KCc + tid*4 + i], accss[i]);
    if (tid < 32) {
        atomicAdd(&g_ca[b*KCc + tid], accca);
        atomicAdd(&g_cs[b*KCc + tid], acccs);
    }
    if (tid < 16) atomicAdd(&g_ecount[b], eacc);
}

// ---------------- K8: spectral trace via CSR ----------------
// One warp per node; 8 nodes per block (grid NNc/8), all in one graph.
__global__ __launch_bounds__(256) void k_trace(const float* __restrict__ s) {
    __shared__ float sacc;
    if (threadIdx.x == 0) sacc = 0.f;
    __syncthreads();
    int n = (blockIdx.x * 256 + threadIdx.x) >> 5;   // global warp id = node id
    int lane = threadIdx.x & 31;
    int rs  = g_rowptr[n];
    int deg = g_degi[n];
    float accv = 0.f;
    for (int base = 0; base < deg; base += 32) {
        int l = base + lane;
        int idx = (l < deg) ? g_csrc[rs + l] : 0;
        int cnt = min(32, deg - base);
#pragma unroll 4
        for (int i = 0; i < cnt; i++) {
            int sn = __shfl_sync(0xffffffffu, idx, i);
            accv += s[(size_t)sn * KCc + lane];
        }
    }
    float p = accv * s[(size_t)n * KCc + lane];
#pragma unroll
    for (int o = 16; o; o >>= 1) p += __shfl_xor_sync(0xffffffffu, p, o);
    if (lane == 0) atomicAdd(&sacc, p);
    __syncthreads();
    if (threadIdx.x == 0) atomicAdd(&g_trace[(blockIdx.x * 8) >> 11], sacc);
}

// ---------------- K9: losses ----------------
__global__ __launch_bounds__(512) void k_losses(float* __restrict__ out_loss) {
    __shared__ float bl[Bg];
    int w = threadIdx.x >> 5, lane = threadIdx.x & 31;
    if (w < Bg) {
        int b = w;
        float m = g_ecount[b] * 0.5f;
        float q = 0.f;
        for (int i = 0; i < 32; i++) {
            float v = g_ss[b*1024 + i*32 + lane];
            q += v * v;
        }
#pragma unroll
        for (int o = 16; o; o >>= 1) q += __shfl_xor_sync(0xffffffffu, q, o);
        float nrm = sqrtf(q);
        float inv_sk = rsqrtf((float)KCc);
        float oo = 0.f;
        for (int i = 0; i < 32; i++) {
            float v = g_ss[b*1024 + i*32 + lane] / nrm - ((i == lane) ? inv_sk : 0.f);
            oo += v * v;
        }
#pragma unroll
        for (int o = 16; o; o >>= 1) oo += __shfl_xor_sync(0xffffffffu, oo, o);
        float cav = g_ca[b*KCc + lane];
        float ca2 = cav * cav;
#pragma unroll
        for (int o = 16; o; o >>= 1) ca2 += __shfl_xor_sync(0xffffffffu, ca2, o);
        float csv = g_cs[b*KCc + lane];
        float cs2 = csv * csv;
#pragma unroll
        for (int o = 16; o; o >>= 1) cs2 += __shfl_xor_sync(0xffffffffu, cs2, o);
        if (lane == 0) {
            float spec = -(g_trace[b] - ca2 / (2.f * m)) / (2.f * m);
            float ortho = sqrtf(oo);
            float clus = sqrtf(cs2) / (float)NPGc * sqrtf((float)KCc) - 1.f;
            bl[b] = spec + ortho + clus;
        }
    }
    __syncthreads();
    if (threadIdx.x == 0) {
        float t = 0.f;
        for (int i = 0; i < Bg; i++) t += bl[i];
        out_loss[0] = t / (float)Bg;
    }
}

// ---------------- K10: selu + log_softmax of out_x ----------------
__global__ __launch_bounds__(128) void k_outx(float* __restrict__ out) {
    __shared__ float redm[4], reds[4];
    int row = blockIdx.x;
    int t = threadIdx.x;
    int warp = t >> 5, lane = t & 31;
    float v = g_sx[row * HIDc + t];
    const float sc = 1.0507009873554805f, al = 1.6732632423543772f;
    v = (v > 0.f) ? sc * v : sc * al * (expf(v) - 1.f);
    float mx = v;
#pragma unroll
    for (int o = 16; o; o >>= 1) mx = fmaxf(mx, __shfl_xor_sync(0xffffffffu, mx, o));
    if (lane == 0) redm[warp] = mx;
    __syncthreads();
    mx = fmaxf(fmaxf(redm[0], redm[1]), fmaxf(redm[2], redm[3]));
    float e = expf(v - mx);
    float sum = e;
#pragma unroll
    for (int o = 16; o; o >>= 1) sum += __shfl_xor_sync(0xffffffffu, sum, o);
    if (lane == 0) reds[warp] = sum;
    __syncthreads();
    sum = reds[0] + reds[1] + reds[2] + reds[3];
    out[row * HIDc + t] = v - mx - logf(sum);
}

// ---------------- launch ----------------
extern "C" void kernel_launch(void* const* d_in, const int* in_sizes, int n_in,
                              void* d_out, int out_size) {
    int i_x = 0, i_W1 = 4, i_b1 = 5, i_Wp = 6, i_bp = 7, i_ei = 8;
    for (int i = 0; i < n_in; i++) {
        int sz = in_sizes[i];
        if (sz == NNc * CINc)       i_x  = i;
        else if (sz == CINc * HIDc) i_W1 = i;
        else if (sz == HIDc)        i_b1 = i;
        else if (sz == HIDc * KCc)  i_Wp = i;
        else if (sz == KCc)         i_bp = i;
        else if (sz == 2 * EEc)     i_ei = i;
    }
    const float* x   = (const float*)d_in[i_x];
    const float* gnw = (const float*)d_in[1];
    const float* gnb = (const float*)d_in[2];
    const float* gms = (const float*)d_in[3];
    const float* W1  = (const float*)d_in[i_W1];
    const float* b1  = (const float*)d_in[i_b1];
    const float* Wp  = (const float*)d_in[i_Wp];
    const float* bp  = (const float*)d_in[i_bp];
    const void*  ei  = d_in[i_ei];

    float* out = (float*)d_out;
    float* out_loss = out + Bg*KCc*HIDc;          // 65536
    float* out_s    = out + Bg*KCc*HIDc + 1;      // 65537

    k_zero<<<1024, 256>>>();
    k_convert_deg<<<EEc/256, 256>>>(ei);
    k_scan<<<NNc/256, 256>>>();
    k_fill<<<EEc/256, 256>>>();
    k_gn_part<<<dim3(Bg, 16), 256>>>(x);
    k_gemm1<<<NNc/32, 256>>>(x, gnw, gnb, gms, W1);
    k_gather<<<NNc/8, 256>>>();
    k_fin_red<<<dim3(Bg, 16), 256>>>(b1, Wp, bp, out_s);
    k_trace<<<NNc/8, 256>>>(out_s);
    k_losses<<<1, 512>>>(out_loss);
    k_outx<<<Bg*KCc, 128>>>(out);
}

// round 14
// speedup vs baseline: 1.4473x; 1.0500x over previous
#include <cuda_runtime.h>

// Problem constants
#define Bg    16
#define NPGc  2048
#define NNc   32768      // Bg * NPGc
#define CINc  64
#define HIDc  128
#define KCc   32
#define EEc   524288

// ---------------- device scratch ----------------
__device__ float4 g_hlin4[NNc*HIDc/4];    // xn @ W1 (pre-aggregation)
__device__ float4 g_hagg4[NNc*HIDc/4];    // aggregated neighbor sums
#define g_hlin ((float*)g_hlin4)
#define g_hagg ((float*)g_hagg4)

__device__ int   g_src[EEc];
__device__ int   g_dst[EEc];
__device__ int   g_rank[EEc];             // rank of edge within its dst bucket
__device__ int   g_csrc[EEc];             // CSR column (src) indices, grouped by dst
__device__ int   g_degi[NNc];             // in-degree (int)
__device__ int   g_rowptr[NNc];           // CSR row starts
__device__ int   g_counter;               // scan base allocator

__device__ float g_gnsum[Bg*CINc];
__device__ float g_gnsq[Bg*CINc];
__device__ float g_dis[NNc];              // rsqrt(in_deg + 1)
__device__ float g_degsrc[NNc];           // DMoN degrees (out-degree)
__device__ float g_ecount[Bg];
__device__ float g_trace[Bg];             // sum_e dot(s_src, s_dst)
__device__ float g_sx[Bg*KCc*HIDc];       // S^T X per graph
__device__ float g_ss[Bg*KCc*KCc];        // S^T S per graph
__device__ float g_ca[Bg*KCc];            // S^T degrees
__device__ float g_cs[Bg*KCc];            // cluster sizes

// ---------------- f32x2 helpers ----------------
__device__ __forceinline__ unsigned long long f2pack(float x, float y) {
    unsigned long long r;
    asm("mov.b64 %0, {%1, %2};" : "=l"(r) : "f"(x), "f"(y));
    return r;
}
__device__ __forceinline__ unsigned long long ffma2(unsigned long long a,
                                                    unsigned long long b,
                                                    unsigned long long c) {
    unsigned long long d;
    asm("fma.rn.f32x2 %0, %1, %2, %3;" : "=l"(d) : "l"(a), "l"(b), "l"(c));
    return d;
}
__device__ __forceinline__ float2 f2unpack(unsigned long long v) {
    float2 f;
    asm("mov.b64 {%0, %1}, %2;" : "=f"(f.x), "=f"(f.y) : "l"(v));
    return f;
}

// ---------------- K0: zero small accumulators ----------------
__global__ __launch_bounds__(256) void k_zero() {
    int i0 = blockIdx.x * blockDim.x + threadIdx.x;
    int stride = gridDim.x * blockDim.x;
    for (int i = i0; i < NNc; i += stride) { g_degi[i] = 0; g_degsrc[i] = 0.f; }
    for (int i = i0; i < Bg*KCc*HIDc; i += stride) g_sx[i] = 0.f;
    for (int i = i0; i < Bg*KCc*KCc; i += stride) g_ss[i] = 0.f;
    for (int i = i0; i < Bg*KCc; i += stride) { g_ca[i] = 0.f; g_cs[i] = 0.f; }
    for (int i = i0; i < Bg*CINc; i += stride) { g_gnsum[i] = 0.f; g_gnsq[i] = 0.f; }
    if (i0 < Bg) { g_ecount[i0] = 0.f; g_trace[i0] = 0.f; }
    if (i0 == 0) g_counter = 0;
}

// ---------------- K1: edge convert + degree histos + in-bucket rank ----------------
// atomicAdd's return value IS the rank of this edge within its dst bucket.
__global__ __launch_bounds__(256) void k_convert_deg(const void* __restrict__ ebuf) {
    __shared__ int nz;
    int t = threadIdx.x;
    if (t == 0) nz = 0;
    __syncthreads();
    int e = blockIdx.x * 256 + t;
    const int* w32 = (const int*)ebuf;
    unsigned any = __ballot_sync(0xffffffffu, w32[e * 2 + 1] != 0);
    if ((t & 31) == 0 && any) atomicOr(&nz, 1);
    __syncthreads();
    int s, d;
    if (nz == 0) {   // int64
        const long long* p = (const long long*)ebuf;
        s = (int)p[e] & (NNc - 1);
        d = (int)p[EEc + e] & (NNc - 1);
    } else {         // int32
        s = w32[e] & (NNc - 1);
        d = w32[EEc + e] & (NNc - 1);
    }
    g_src[e] = s;
    g_dst[e] = d;
    g_rank[e] = atomicAdd(&g_degi[d], 1);
    atomicAdd(&g_degsrc[s], 1.f);
}

// ---------------- K2: single-pass scan (atomic base) + dis ----------------
__global__ __launch_bounds__(256) void k_scan() {
    __shared__ int sm[256];
    __shared__ int base;
    int t = threadIdx.x;
    int n = blockIdx.x * 256 + t;
    int d = g_degi[n];
    sm[t] = d;
    __syncthreads();
    for (int o = 1; o < 256; o <<= 1) {
        int a = (t >= o) ? sm[t - o] : 0;
        __syncthreads();
        sm[t] += a;
        __syncthreads();
    }
    if (t == 255) base = atomicAdd(&g_counter, sm[255]);
    __syncthreads();
    g_rowptr[n] = base + sm[t] - d;
    g_dis[n] = rsqrtf((float)d + 1.f);
}

// ---------------- K3: atomic-free CSR fill ----------------
__global__ __launch_bounds__(256) void k_fill() {
    int e = blockIdx.x * 256 + threadIdx.x;   // grid 2048
    int d = g_dst[e];
    g_csrc[g_rowptr[d] + g_rank[e]] = g_src[e];
}

// ---------------- K4: GraphNorm partial sums ----------------
__global__ __launch_bounds__(256) void k_gn_part(const float* __restrict__ x) {
    __shared__ float ssum[256], ssq[256];
    int b = blockIdx.x;
    int c = threadIdx.x & 63, r0 = threadIdx.x >> 6;
    const float* xb = x + (size_t)b * NPGc * CINc + (size_t)blockIdx.y * 128 * CINc;
    float s = 0.f, q = 0.f;
    for (int r = r0; r < 128; r += 4) {
        float v = xb[r * CINc + c];
        s += v; q += v * v;
    }
    ssum[threadIdx.x] = s; ssq[threadIdx.x] = q;
    __syncthreads();
    if (threadIdx.x < 64) {
        s = ssum[c] + ssum[c+64] + ssum[c+128] + ssum[c+192];
        q = ssq[c] + ssq[c+64] + ssq[c+128] + ssq[c+192];
        atomicAdd(&g_gnsum[b*CINc + c], s);
        atomicAdd(&g_gnsq[b*CINc + c], q);
    }
}

// ---------------- K5: GN finalize (per-block) + apply + GEMM (f32x2, 32-node tiles) ----------------
__global__ __launch_bounds__(256) void k_gemm1(const float* __restrict__ x,
                                               const float* __restrict__ gnw,
                                               const float* __restrict__ gnb,
                                               const float* __restrict__ gms,
                                               const float* __restrict__ W1) {
    __shared__ float Ws[CINc][HIDc];     // 32 KB
    __shared__ float Xs[32][CINc + 1];   // 8.1 KB
    __shared__ float sshift[CINc], sscale[CINc];
    int n0 = blockIdx.x * 32;
    int b = n0 / NPGc;
    if (threadIdx.x < CINc) {
        int c = threadIdx.x;
        float mean = g_gnsum[b*CINc + c] * (1.f / NPGc);
        float ms = gms[c];
        float var = g_gnsq[b*CINc + c] * (1.f / NPGc)
                  - 2.f * ms * mean * mean + ms * ms * mean * mean;
        sshift[c] = mean * ms;
        sscale[c] = gnw[c] * rsqrtf(var + 1e-5f);
    }
    for (int i = threadIdx.x; i < CINc * HIDc; i += 256)
        Ws[i >> 7][i & 127] = W1[i];
    __syncthreads();
    for (int i = threadIdx.x; i < 32 * CINc; i += 256) {
        int r = i >> 6, c = i & 63;
        float v = x[(size_t)(n0 + r) * CINc + c];
        Xs[r][c] = (v - sshift[c]) * sscale[c] + gnb[c];
    }
    __syncthreads();

    int q = threadIdx.x & 7;
    int jg = threadIdx.x >> 3;
    unsigned long long acc2[4][2];
#pragma unroll
    for (int i = 0; i < 4; i++) { acc2[i][0] = 0ull; acc2[i][1] = 0ull; }

    for (int k = 0; k < CINc; k++) {
        unsigned long long w01 = *(const unsigned long long*)&Ws[k][jg*4];
        unsigned long long w23 = *(const unsigned long long*)&Ws[k][jg*4+2];
#pragma unroll
        for (int i = 0; i < 4; i++) {
            float a = Xs[q*4+i][k];
            unsigned long long a2 = f2pack(a, a);
            acc2[i][0] = ffma2(a2, w01, acc2[i][0]);
            acc2[i][1] = ffma2(a2, w23, acc2[i][1]);
        }
    }
#pragma unroll
    for (int i = 0; i < 4; i++) {
        float2 f01 = f2unpack(acc2[i][0]);
        float2 f23 = f2unpack(acc2[i][1]);
        g_hlin4[(size_t)(n0 + q*4 + i) * (HIDc/4) + jg] =
            make_float4(f01.x, f01.y, f23.x, f23.y);
    }
}

// ---------------- K6: CSR gather with shuffled index prefetch ----------------
__global__ __launch_bounds__(256) void k_gather() {
    int n = (blockIdx.x * 256 + threadIdx.x) >> 5;
    int lane = threadIdx.x & 31;
    if (n >= NNc) return;
    int rs  = g_rowptr[n];
    int deg = g_degi[n];
    float disd = g_dis[n];
    unsigned long long a01 = 0ull, a23 = 0ull;
    for (int base = 0; base < deg; base += 32) {
        int l = base + lane;
        int idx = 0; float cl = 0.f;
        if (l < deg) {
            idx = g_csrc[rs + l];
            cl = disd * g_dis[idx];
        }
        int cnt = min(32, deg - base);
#pragma unroll 4
        for (int i = 0; i < cnt; i++) {
            int s  = __shfl_sync(0xffffffffu, idx, i);
            float c = __shfl_sync(0xffffffffu, cl, i);
            float4 v = g_hlin4[(size_t)s * (HIDc/4) + lane];
            unsigned long long c2 = f2pack(c, c);
            a01 = ffma2(c2, f2pack(v.x, v.y), a01);
            a23 = ffma2(c2, f2pack(v.z, v.w), a23);
        }
    }
    float2 f01 = f2unpack(a01), f23 = f2unpack(a23);
    g_hagg4[(size_t)n * (HIDc/4) + lane] = make_float4(f01.x, f01.y, f23.x, f23.y);
}

// ---------------- K7: fused finalize-h + softmax + node reductions ----------------
__global__ __launch_bounds__(256) void k_fin_red(const float* __restrict__ b1,
                                                 const float* __restrict__ Wp,
                                                 const float* __restrict__ bp,
                                                 float* __restrict__ out_s) {
    __shared__ float Wps[HIDc * KCc];  // 16 KB
    __shared__ float sH[16][HIDc];     // 8 KB
    __shared__ float sS[16][KCc];      // 2 KB
    __shared__ float sD[16];
    __shared__ float b1s[HIDc];
    __shared__ float bps[KCc];
    int tid = threadIdx.x;
    int b = blockIdx.x;
    int n0 = b * NPGc + blockIdx.y * 128;
    for (int i = tid; i < HIDc * KCc; i += 256) Wps[i] = Wp[i];
    if (tid < HIDc) b1s[tid] = b1[tid];
    if (tid < KCc)  bps[tid] = bp[tid];

    int warp = tid >> 5, lane = tid & 31;
    int k = tid >> 3, j8 = tid & 7;
    unsigned long long accx2[8];
#pragma unroll
    for (int i = 0; i < 8; i++) accx2[i] = 0ull;
    float accss[4] = {0.f, 0.f, 0.f, 0.f};
    float accca = 0.f, acccs = 0.f, eacc = 0.f;

    for (int tile = 0; tile < 8; tile++) {
        int base = n0 + tile * 16;
        __syncthreads();
        for (int idx = tid; idx < 16 * HIDc; idx += 256) {
            int nl = idx >> 7, j = idx & 127;
            int n = base + nl;
            float dis = g_dis[n];
            float v = g_hagg[(size_t)n*HIDc + j]
                    + dis * dis * g_hlin[(size_t)n*HIDc + j] + b1s[j];
            sH[nl][j] = fmaxf(v, 0.f);
        }
        if (tid < 16) sD[tid] = g_degsrc[base + tid];
        __syncthreads();
#pragma unroll
        for (int u = 0; u < 2; u++) {
            int nl = warp * 2 + u;
            float acc = bps[lane];
#pragma unroll 8
            for (int j = 0; j < HIDc; j++)
                acc += sH[nl][j] * Wps[j * KCc + lane];
            float m = acc;
#pragma unroll
            for (int o = 16; o; o >>= 1) m = fmaxf(m, __shfl_xor_sync(0xffffffffu, m, o));
            float e = expf(acc - m);
            float sum = e;
#pragma unroll
            for (int o = 16; o; o >>= 1) sum += __shfl_xor_sync(0xffffffffu, sum, o);
            float sv = e / sum;
            sS[nl][lane] = sv;
            out_s[(size_t)(base + nl) * KCc + lane] = sv;
        }
        __syncthreads();
        if (tid < 16) eacc += sD[tid];
#pragma unroll 4
        for (int nn = 0; nn < 16; nn++) {
            float sk = sS[nn][k];
            unsigned long long sk2 = f2pack(sk, sk);
            const unsigned long long* row = (const unsigned long long*)&sH[nn][0];
#pragma unroll
            for (int jj = 0; jj < 8; jj++)
                accx2[jj] = ffma2(sk2, row[j8 + jj * 8], accx2[jj]);
#pragma unroll
            for (int i = 0; i < 4; i++) {
                int idx = tid * 4 + i;
                accss[i] += sS[nn][idx >> 5] * sS[nn][idx & 31];
            }
            if (tid < 32) {
                float sv = sS[nn][tid];
                accca += sv * sD[nn];
                acccs += sv;
            }
        }
    }
#pragma unroll
    for (int jj = 0; jj < 8; jj++) {
        float2 r = f2unpack(accx2[jj]);
        atomicAdd(&g_sx[b*KCc*HIDc + k*HIDc + 2*j8 + 16*jj], r.x);
        atomicAdd(&g_sx[b*KCc*HIDc + k*HIDc + 2*j8 + 16*jj + 1], r.y);
    }
#pragma unroll
    for (int i = 0; i < 4; i++)
        atomicAdd(&g_ss[b*KCc*KCc + tid*4 + i], accss[i]);
    if (tid < 32) {
        atomicAdd(&g_ca[b*KCc + tid], accca);
        atomicAdd(&g_cs[b*KCc + tid], acccs);
    }
    if (tid < 16) atomicAdd(&g_ecount[b], eacc);
}

// ---------------- K8: spectral trace via CSR ----------------
// One warp per node; 8 nodes per block (grid NNc/8), all in one graph.
__global__ __launch_bounds__(256) void k_trace(const float* __restrict__ s) {
    __shared__ float sacc;
    if (threadIdx.x == 0) sacc = 0.f;
    __syncthreads();
    int n = (blockIdx.x * 256 + threadIdx.x) >> 5;   // global warp id = node id
    int lane = threadIdx.x & 31;
    int rs  = g_rowptr[n];
    int deg = g_degi[n];
    float accv = 0.f;
    for (int base = 0; base < deg; base += 32) {
        int l = base + lane;
        int idx = (l < deg) ? g_csrc[rs + l] : 0;
        int cnt = min(32, deg - base);
#pragma unroll 4
        for (int i = 0; i < cnt; i++) {
            int sn = __shfl_sync(0xffffffffu, idx, i);
            accv += s[(size_t)sn * KCc + lane];
        }
    }
    float p = accv * s[(size_t)n * KCc + lane];
#pragma unroll
    for (int o = 16; o; o >>= 1) p += __shfl_xor_sync(0xffffffffu, p, o);
    if (lane == 0) atomicAdd(&sacc, p);
    __syncthreads();
    if (threadIdx.x == 0) atomicAdd(&g_trace[(blockIdx.x * 8) >> 11], sacc);
}

// ---------------- K9: losses ----------------
__global__ __launch_bounds__(512) void k_losses(float* __restrict__ out_loss) {
    __shared__ float bl[Bg];
    int w = threadIdx.x >> 5, lane = threadIdx.x & 31;
    if (w < Bg) {
        int b = w;
        float m = g_ecount[b] * 0.5f;
        float q = 0.f;
        for (int i = 0; i < 32; i++) {
            float v = g_ss[b*1024 + i*32 + lane];
            q += v * v;
        }
#pragma unroll
        for (int o = 16; o; o >>= 1) q += __shfl_xor_sync(0xffffffffu, q, o);
        float nrm = sqrtf(q);
        float inv_sk = rsqrtf((float)KCc);
        float oo = 0.f;
        for (int i = 0; i < 32; i++) {
            float v = g_ss[b*1024 + i*32 + lane] / nrm - ((i == lane) ? inv_sk : 0.f);
            oo += v * v;
        }
#pragma unroll
        for (int o = 16; o; o >>= 1) oo += __shfl_xor_sync(0xffffffffu, oo, o);
        float cav = g_ca[b*KCc + lane];
        float ca2 = cav * cav;
#pragma unroll
        for (int o = 16; o; o >>= 1) ca2 += __shfl_xor_sync(0xffffffffu, ca2, o);
        float csv = g_cs[b*KCc + lane];
        float cs2 = csv * csv;
#pragma unroll
        for (int o = 16; o; o >>= 1) cs2 += __shfl_xor_sync(0xffffffffu, cs2, o);
        if (lane == 0) {
            float spec = -(g_trace[b] - ca2 / (2.f * m)) / (2.f * m);
            float ortho = sqrtf(oo);
            float clus = sqrtf(cs2) / (float)NPGc * sqrtf((float)KCc) - 1.f;
            bl[b] = spec + ortho + clus;
        }
    }
    __syncthreads();
    if (threadIdx.x == 0) {
        float t = 0.f;
        for (int i = 0; i < Bg; i++) t += bl[i];
        out_loss[0] = t / (float)Bg;
    }
}

// ---------------- K10: selu + log_softmax of out_x ----------------
__global__ __launch_bounds__(128) void k_outx(float* __restrict__ out) {
    __shared__ float redm[4], reds[4];
    int row = blockIdx.x;
    int t = threadIdx.x;
    int warp = t >> 5, lane = t & 31;
    float v = g_sx[row * HIDc + t];
    const float sc = 1.0507009873554805f, al = 1.6732632423543772f;
    v = (v > 0.f) ? sc * v : sc * al * (expf(v) - 1.f);
    float mx = v;
#pragma unroll
    for (int o = 16; o; o >>= 1) mx = fmaxf(mx, __shfl_xor_sync(0xffffffffu, mx, o));
    if (lane == 0) redm[warp] = mx;
    __syncthreads();
    mx = fmaxf(fmaxf(redm[0], redm[1]), fmaxf(redm[2], redm[3]));
    float e = expf(v - mx);
    float sum = e;
#pragma unroll
    for (int o = 16; o; o >>= 1) sum += __shfl_xor_sync(0xffffffffu, sum, o);
    if (lane == 0) reds[warp] = sum;
    __syncthreads();
    sum = reds[0] + reds[1] + reds[2] + reds[3];
    out[row * HIDc + t] = v - mx - logf(sum);
}

// ---------------- launch (two-stream fork-join) ----------------
extern "C" void kernel_launch(void* const* d_in, const int* in_sizes, int n_in,
                              void* d_out, int out_size) {
    int i_x = 0, i_W1 = 4, i_b1 = 5, i_Wp = 6, i_bp = 7, i_ei = 8;
    for (int i = 0; i < n_in; i++) {
        int sz = in_sizes[i];
        if (sz == NNc * CINc)       i_x  = i;
        else if (sz == CINc * HIDc) i_W1 = i;
        else if (sz == HIDc)        i_b1 = i;
        else if (sz == HIDc * KCc)  i_Wp = i;
        else if (sz == KCc)         i_bp = i;
        else if (sz == 2 * EEc)     i_ei = i;
    }
    const float* x   = (const float*)d_in[i_x];
    const float* gnw = (const float*)d_in[1];
    const float* gnb = (const float*)d_in[2];
    const float* gms = (const float*)d_in[3];
    const float* W1  = (const float*)d_in[i_W1];
    const float* b1  = (const float*)d_in[i_b1];
    const float* Wp  = (const float*)d_in[i_Wp];
    const float* bp  = (const float*)d_in[i_bp];
    const void*  ei  = d_in[i_ei];

    float* out = (float*)d_out;
    float* out_loss = out + Bg*KCc*HIDc;          // 65536
    float* out_s    = out + Bg*KCc*HIDc + 1;      // 65537

    cudaStream_t s2;
    cudaEvent_t evFork, evJoin;
    cudaStreamCreateWithFlags(&s2, cudaStreamNonBlocking);
    cudaEventCreateWithFlags(&evFork, cudaEventDisableTiming);
    cudaEventCreateWithFlags(&evJoin, cudaEventDisableTiming);

    // main stream: zero, then fork
    k_zero<<<1024, 256>>>();
    cudaEventRecord(evFork, 0);
    cudaStreamWaitEvent(s2, evFork, 0);

    // x chain on s2 (gn_part + gemm1 overlap the edge chain)
    k_gn_part<<<dim3(Bg, 16), 256, 0, s2>>>(x);
    k_gemm1<<<NNc/32, 256, 0, s2>>>(x, gnw, gnb, gms, W1);
    cudaEventRecord(evJoin, s2);

    // edge chain on main stream
    k_convert_deg<<<EEc/256, 256>>>(ei);
    k_scan<<<NNc/256, 256>>>();
    k_fill<<<EEc/256, 256>>>();

    // join: gather needs both chains
    cudaStreamWaitEvent(0, evJoin, 0);
    k_gather<<<NNc/8, 256>>>();
    k_fin_red<<<dim3(Bg, 16), 256>>>(b1, Wp, bp, out_s);
    k_trace<<<NNc/8, 256>>>(out_s);
    k_losses<<<1, 512>>>(out_loss);
    k_outx<<<Bg*KCc, 128>>>(out);

    cudaEventDestroy(evFork);
    cudaEventDestroy(evJoin);
    cudaStreamDestroy(s2);
}

// round 15
// speedup vs baseline: 1.5816x; 1.0928x over previous
#include <cuda_runtime.h>

// Problem constants
#define Bg    16
#define NPGc  2048
#define NNc   32768      // Bg * NPGc
#define CINc  64
#define HIDc  128
#define KCc   32
#define EEc   524288

// ---------------- device scratch ----------------
__device__ float4 g_hlin4[NNc*HIDc/4];    // xn @ W1 (pre-aggregation)
__device__ float4 g_hagg4[NNc*HIDc/4];    // aggregated neighbor sums
#define g_hlin ((float*)g_hlin4)
#define g_hagg ((float*)g_hagg4)

__device__ int   g_src[EEc];
__device__ int   g_dst[EEc];
__device__ int   g_rank[EEc];             // rank of edge within its dst bucket
__device__ int   g_csrc[EEc];             // CSR column (src) indices, grouped by dst
__device__ int   g_degi[NNc];             // in-degree (int)
__device__ int   g_rowptr[NNc];           // CSR row starts
__device__ int   g_counter;               // scan base allocator

__device__ float g_gnsum[Bg*CINc];
__device__ float g_gnsq[Bg*CINc];
__device__ float g_dis[NNc];              // rsqrt(in_deg + 1)
__device__ float g_degsrc[NNc];           // DMoN degrees (out-degree)
__device__ float g_ecount[Bg];
__device__ float g_trace[Bg];             // sum_e dot(s_src, s_dst)
__device__ float g_sx[Bg*KCc*HIDc];       // S^T X per graph
__device__ float g_ss[Bg*KCc*KCc];        // S^T S per graph
__device__ float g_ca[Bg*KCc];            // S^T degrees
__device__ float g_cs[Bg*KCc];            // cluster sizes

// ---------------- f32x2 helpers ----------------
__device__ __forceinline__ unsigned long long f2pack(float x, float y) {
    unsigned long long r;
    asm("mov.b64 %0, {%1, %2};" : "=l"(r) : "f"(x), "f"(y));
    return r;
}
__device__ __forceinline__ unsigned long long ffma2(unsigned long long a,
                                                    unsigned long long b,
                                                    unsigned long long c) {
    unsigned long long d;
    asm("fma.rn.f32x2 %0, %1, %2, %3;" : "=l"(d) : "l"(a), "l"(b), "l"(c));
    return d;
}
__device__ __forceinline__ float2 f2unpack(unsigned long long v) {
    float2 f;
    asm("mov.b64 {%0, %1}, %2;" : "=f"(f.x), "=f"(f.y) : "l"(v));
    return f;
}

// ---------------- K0: zero small accumulators ----------------
__global__ __launch_bounds__(256) void k_zero() {
    int i0 = blockIdx.x * blockDim.x + threadIdx.x;
    int stride = gridDim.x * blockDim.x;
    for (int i = i0; i < NNc; i += stride) { g_degi[i] = 0; g_degsrc[i] = 0.f; }
    for (int i = i0; i < Bg*KCc*HIDc; i += stride) g_sx[i] = 0.f;
    for (int i = i0; i < Bg*KCc*KCc; i += stride) g_ss[i] = 0.f;
    for (int i = i0; i < Bg*KCc; i += stride) { g_ca[i] = 0.f; g_cs[i] = 0.f; }
    for (int i = i0; i < Bg*CINc; i += stride) { g_gnsum[i] = 0.f; g_gnsq[i] = 0.f; }
    if (i0 < Bg) { g_ecount[i0] = 0.f; g_trace[i0] = 0.f; }
    if (i0 == 0) g_counter = 0;
}

// ---------------- K1: edge convert + in-degree + in-bucket rank ----------------
// atomicAdd's return value IS the rank of this edge within its dst bucket.
// (degsrc histogram moved to k_fill to shorten this kernel's atomic load.)
__global__ __launch_bounds__(256) void k_convert_deg(const void* __restrict__ ebuf) {
    __shared__ int nz;
    int t = threadIdx.x;
    if (t == 0) nz = 0;
    __syncthreads();
    int e = blockIdx.x * 256 + t;
    const int* w32 = (const int*)ebuf;
    unsigned any = __ballot_sync(0xffffffffu, w32[e * 2 + 1] != 0);
    if ((t & 31) == 0 && any) atomicOr(&nz, 1);
    __syncthreads();
    int s, d;
    if (nz == 0) {   // int64
        const long long* p = (const long long*)ebuf;
        s = (int)p[e] & (NNc - 1);
        d = (int)p[EEc + e] & (NNc - 1);
    } else {         // int32
        s = w32[e] & (NNc - 1);
        d = w32[EEc + e] & (NNc - 1);
    }
    g_src[e] = s;
    g_dst[e] = d;
    g_rank[e] = atomicAdd(&g_degi[d], 1);
}

// ---------------- K2: single-pass scan (atomic base) + dis ----------------
__global__ __launch_bounds__(256) void k_scan() {
    __shared__ int sm[256];
    __shared__ int base;
    int t = threadIdx.x;
    int n = blockIdx.x * 256 + t;
    int d = g_degi[n];
    sm[t] = d;
    __syncthreads();
    for (int o = 1; o < 256; o <<= 1) {
        int a = (t >= o) ? sm[t - o] : 0;
        __syncthreads();
        sm[t] += a;
        __syncthreads();
    }
    if (t == 255) base = atomicAdd(&g_counter, sm[255]);
    __syncthreads();
    g_rowptr[n] = base + sm[t] - d;
    g_dis[n] = rsqrtf((float)d + 1.f);
}

// ---------------- K3: atomic-free CSR fill + out-degree histogram ----------------
__global__ __launch_bounds__(256) void k_fill() {
    int e = blockIdx.x * 256 + threadIdx.x;   // grid 2048
    int d = g_dst[e];
    int s = g_src[e];
    g_csrc[g_rowptr[d] + g_rank[e]] = s;
    atomicAdd(&g_degsrc[s], 1.f);
}

// ---------------- K4: GraphNorm partial sums ----------------
__global__ __launch_bounds__(256) void k_gn_part(const float* __restrict__ x) {
    __shared__ float ssum[256], ssq[256];
    int b = blockIdx.x;
    int c = threadIdx.x & 63, r0 = threadIdx.x >> 6;
    const float* xb = x + (size_t)b * NPGc * CINc + (size_t)blockIdx.y * 128 * CINc;
    float s = 0.f, q = 0.f;
    for (int r = r0; r < 128; r += 4) {
        float v = xb[r * CINc + c];
        s += v; q += v * v;
    }
    ssum[threadIdx.x] = s; ssq[threadIdx.x] = q;
    __syncthreads();
    if (threadIdx.x < 64) {
        s = ssum[c] + ssum[c+64] + ssum[c+128] + ssum[c+192];
        q = ssq[c] + ssq[c+64] + ssq[c+128] + ssq[c+192];
        atomicAdd(&g_gnsum[b*CINc + c], s);
        atomicAdd(&g_gnsq[b*CINc + c], q);
    }
}

// ---------------- K5: GN finalize (per-block) + apply + GEMM (f32x2, 32-node tiles) ----------------
__global__ __launch_bounds__(256) void k_gemm1(const float* __restrict__ x,
                                               const float* __restrict__ gnw,
                                               const float* __restrict__ gnb,
                                               const float* __restrict__ gms,
                                               const float* __restrict__ W1) {
    __shared__ float Ws[CINc][HIDc];     // 32 KB
    __shared__ float Xs[32][CINc + 1];   // 8.1 KB
    __shared__ float sshift[CINc], sscale[CINc];
    int n0 = blockIdx.x * 32;
    int b = n0 / NPGc;
    if (threadIdx.x < CINc) {
        int c = threadIdx.x;
        float mean = g_gnsum[b*CINc + c] * (1.f / NPGc);
        float ms = gms[c];
        float var = g_gnsq[b*CINc + c] * (1.f / NPGc)
                  - 2.f * ms * mean * mean + ms * ms * mean * mean;
        sshift[c] = mean * ms;
        sscale[c] = gnw[c] * rsqrtf(var + 1e-5f);
    }
    for (int i = threadIdx.x; i < CINc * HIDc; i += 256)
        Ws[i >> 7][i & 127] = W1[i];
    __syncthreads();
    for (int i = threadIdx.x; i < 32 * CINc; i += 256) {
        int r = i >> 6, c = i & 63;
        float v = x[(size_t)(n0 + r) * CINc + c];
        Xs[r][c] = (v - sshift[c]) * sscale[c] + gnb[c];
    }
    __syncthreads();

    int q = threadIdx.x & 7;
    int jg = threadIdx.x >> 3;
    unsigned long long acc2[4][2];
#pragma unroll
    for (int i = 0; i < 4; i++) { acc2[i][0] = 0ull; acc2[i][1] = 0ull; }

    for (int k = 0; k < CINc; k++) {
        unsigned long long w01 = *(const unsigned long long*)&Ws[k][jg*4];
        unsigned long long w23 = *(const unsigned long long*)&Ws[k][jg*4+2];
#pragma unroll
        for (int i = 0; i < 4; i++) {
            float a = Xs[q*4+i][k];
            unsigned long long a2 = f2pack(a, a);
            acc2[i][0] = ffma2(a2, w01, acc2[i][0]);
            acc2[i][1] = ffma2(a2, w23, acc2[i][1]);
        }
    }
#pragma unroll
    for (int i = 0; i < 4; i++) {
        float2 f01 = f2unpack(acc2[i][0]);
        float2 f23 = f2unpack(acc2[i][1]);
        g_hlin4[(size_t)(n0 + q*4 + i) * (HIDc/4) + jg] =
            make_float4(f01.x, f01.y, f23.x, f23.y);
    }
}

// ---------------- K6: CSR gather with shuffled index prefetch ----------------
__global__ __launch_bounds__(256) void k_gather() {
    int n = (blockIdx.x * 256 + threadIdx.x) >> 5;
    int lane = threadIdx.x & 31;
    if (n >= NNc) return;
    int rs  = g_rowptr[n];
    int deg = g_degi[n];
    float disd = g_dis[n];
    unsigned long long a01 = 0ull, a23 = 0ull;
    for (int base = 0; base < deg; base += 32) {
        int l = base + lane;
        int idx = 0; float cl = 0.f;
        if (l < deg) {
            idx = g_csrc[rs + l];
            cl = disd * g_dis[idx];
        }
        int cnt = min(32, deg - base);
#pragma unroll 4
        for (int i = 0; i < cnt; i++) {
            int s  = __shfl_sync(0xffffffffu, idx, i);
            float c = __shfl_sync(0xffffffffu, cl, i);
            float4 v = g_hlin4[(size_t)s * (HIDc/4) + lane];
            unsigned long long c2 = f2pack(c, c);
            a01 = ffma2(c2, f2pack(v.x, v.y), a01);
            a23 = ffma2(c2, f2pack(v.z, v.w), a23);
        }
    }
    float2 f01 = f2unpack(a01), f23 = f2unpack(a23);
    g_hagg4[(size_t)n * (HIDc/4) + lane] = make_float4(f01.x, f01.y, f23.x, f23.y);
}

// ---------------- K7: fused finalize-h + softmax + node reductions ----------------
// grid (Bg, 64): 32 nodes per block in 2 tiles (4x parallelism vs R14).
__global__ __launch_bounds__(256) void k_fin_red(const float* __restrict__ b1,
                                                 const float* __restrict__ Wp,
                                                 const float* __restrict__ bp,
                                                 float* __restrict__ out_s) {
    __shared__ float Wps[HIDc * KCc];  // 16 KB
    __shared__ float sH[16][HIDc];     // 8 KB
    __shared__ float sS[16][KCc];      // 2 KB
    __shared__ float sD[16];
    __shared__ float b1s[HIDc];
    __shared__ float bps[KCc];
    int tid = threadIdx.x;
    int b = blockIdx.x;
    int n0 = b * NPGc + blockIdx.y * 32;
    for (int i = tid; i < HIDc * KCc; i += 256) Wps[i] = Wp[i];
    if (tid < HIDc) b1s[tid] = b1[tid];
    if (tid < KCc)  bps[tid] = bp[tid];

    int warp = tid >> 5, lane = tid & 31;
    int k = tid >> 3, j8 = tid & 7;
    unsigned long long accx2[8];
#pragma unroll
    for (int i = 0; i < 8; i++) accx2[i] = 0ull;
    float accss[4] = {0.f, 0.f, 0.f, 0.f};
    float accca = 0.f, acccs = 0.f, eacc = 0.f;

    for (int tile = 0; tile < 2; tile++) {
        int base = n0 + tile * 16;
        __syncthreads();
        for (int idx = tid; idx < 16 * HIDc; idx += 256) {
            int nl = idx >> 7, j = idx & 127;
            int n = base + nl;
            float dis = g_dis[n];
            float v = g_hagg[(size_t)n*HIDc + j]
                    + dis * dis * g_hlin[(size_t)n*HIDc + j] + b1s[j];
            sH[nl][j] = fmaxf(v, 0.f);
        }
        if (tid < 16) sD[tid] = g_degsrc[base + tid];
        __syncthreads();
#pragma unroll
        for (int u = 0; u < 2; u++) {
            int nl = warp * 2 + u;
            float acc = bps[lane];
#pragma unroll 8
            for (int j = 0; j < HIDc; j++)
                acc += sH[nl][j] * Wps[j * KCc + lane];
            float m = acc;
#pragma unroll
            for (int o = 16; o; o >>= 1) m = fmaxf(m, __shfl_xor_sync(0xffffffffu, m, o));
            float e = expf(acc - m);
            float sum = e;
#pragma unroll
            for (int o = 16; o; o >>= 1) sum += __shfl_xor_sync(0xffffffffu, sum, o);
            float sv = e / sum;
            sS[nl][lane] = sv;
            out_s[(size_t)(base + nl) * KCc + lane] = sv;
        }
        __syncthreads();
        if (tid < 16) eacc += sD[tid];
#pragma unroll 4
        for (int nn = 0; nn < 16; nn++) {
            float sk = sS[nn][k];
            unsigned long long sk2 = f2pack(sk, sk);
            const unsigned long long* row = (const unsigned long long*)&sH[nn][0];
#pragma unroll
            for (int jj = 0; jj < 8; jj++)
                accx2[jj] = ffma2(sk2, row[j8 + jj * 8], accx2[jj]);
#pragma unroll
            for (int i = 0; i < 4; i++) {
                int idx = tid * 4 + i;
                accss[i] += sS[nn][idx >> 5] * sS[nn][idx & 31];
            }
            if (tid < 32) {
                float sv = sS[nn][tid];
                accca += sv * sD[nn];
                acccs += sv;
            }
        }
    }
#pragma unroll
    for (int jj = 0; jj < 8; jj++) {
        float2 r = f2unpack(accx2[jj]);
        atomicAdd(&g_sx[b*KCc*HIDc + k*HIDc + 2*j8 + 16*jj], r.x);
        atomicAdd(&g_sx[b*KCc*HIDc + k*HIDc + 2*j8 + 16*jj + 1], r.y);
    }
#pragma unroll
    for (int i = 0; i < 4; i++)
        atomicAdd(&g_ss[b*KCc*KCc + tid*4 + i], accss[i]);
    if (tid < 32) {
        atomicAdd(&g_ca[b*KCc + tid], accca);
        atomicAdd(&g_cs[b*KCc + tid], acccs);
    }
    if (tid < 16) atomicAdd(&g_ecount[b], eacc);
}

// ---------------- K8: spectral trace via CSR ----------------
__global__ __launch_bounds__(256) void k_trace(const float* __restrict__ s) {
    __shared__ float sacc;
    if (threadIdx.x == 0) sacc = 0.f;
    __syncthreads();
    int n = (blockIdx.x * 256 + threadIdx.x) >> 5;   // global warp id = node id
    int lane = threadIdx.x & 31;
    int rs  = g_rowptr[n];
    int deg = g_degi[n];
    float accv = 0.f;
    for (int base = 0; base < deg; base += 32) {
        int l = base + lane;
        int idx = (l < deg) ? g_csrc[rs + l] : 0;
        int cnt = min(32, deg - base);
#pragma unroll 4
        for (int i = 0; i < cnt; i++) {
            int sn = __shfl_sync(0xffffffffu, idx, i);
            accv += s[(size_t)sn * KCc + lane];
        }
    }
    float p = accv * s[(size_t)n * KCc + lane];
#pragma unroll
    for (int o = 16; o; o >>= 1) p += __shfl_xor_sync(0xffffffffu, p, o);
    if (lane == 0) atomicAdd(&sacc, p);
    __syncthreads();
    if (threadIdx.x == 0) atomicAdd(&g_trace[(blockIdx.x * 8) >> 11], sacc);
}

// ---------------- K9: losses ----------------
__global__ __launch_bounds__(512) void k_losses(float* __restrict__ out_loss) {
    __shared__ float bl[Bg];
    int w = threadIdx.x >> 5, lane = threadIdx.x & 31;
    if (w < Bg) {
        int b = w;
        float m = g_ecount[b] * 0.5f;
        float q = 0.f;
        for (int i = 0; i < 32; i++) {
            float v = g_ss[b*1024 + i*32 + lane];
            q += v * v;
        }
#pragma unroll
        for (int o = 16; o; o >>= 1) q += __shfl_xor_sync(0xffffffffu, q, o);
        float nrm = sqrtf(q);
        float inv_sk = rsqrtf((float)KCc);
        float oo = 0.f;
        for (int i = 0; i < 32; i++) {
            float v = g_ss[b*1024 + i*32 + lane] / nrm - ((i == lane) ? inv_sk : 0.f);
            oo += v * v;
        }
#pragma unroll
        for (int o = 16; o; o >>= 1) oo += __shfl_xor_sync(0xffffffffu, oo, o);
        float cav = g_ca[b*KCc + lane];
        float ca2 = cav * cav;
#pragma unroll
        for (int o = 16; o; o >>= 1) ca2 += __shfl_xor_sync(0xffffffffu, ca2, o);
        float csv = g_cs[b*KCc + lane];
        float cs2 = csv * csv;
#pragma unroll
        for (int o = 16; o; o >>= 1) cs2 += __shfl_xor_sync(0xffffffffu, cs2, o);
        if (lane == 0) {
            float spec = -(g_trace[b] - ca2 / (2.f * m)) / (2.f * m);
            float ortho = sqrtf(oo);
            float clus = sqrtf(cs2) / (float)NPGc * sqrtf((float)KCc) - 1.f;
            bl[b] = spec + ortho + clus;
        }
    }
    __syncthreads();
    if (threadIdx.x == 0) {
        float t = 0.f;
        for (int i = 0; i < Bg; i++) t += bl[i];
        out_loss[0] = t / (float)Bg;
    }
}

// ---------------- K10: selu + log_softmax of out_x ----------------
__global__ __launch_bounds__(128) void k_outx(float* __restrict__ out) {
    __shared__ float redm[4], reds[4];
    int row = blockIdx.x;
    int t = threadIdx.x;
    int warp = t >> 5, lane = t & 31;
    float v = g_sx[row * HIDc + t];
    const float sc = 1.0507009873554805f, al = 1.6732632423543772f;
    v = (v > 0.f) ? sc * v : sc * al * (expf(v) - 1.f);
    float mx = v;
#pragma unroll
    for (int o = 16; o; o >>= 1) mx = fmaxf(mx, __shfl_xor_sync(0xffffffffu, mx, o));
    if (lane == 0) redm[warp] = mx;
    __syncthreads();
    mx = fmaxf(fmaxf(redm[0], redm[1]), fmaxf(redm[2], redm[3]));
    float e = expf(v - mx);
    float sum = e;
#pragma unroll
    for (int o = 16; o; o >>= 1) sum += __shfl_xor_sync(0xffffffffu, sum, o);
    if (lane == 0) reds[warp] = sum;
    __syncthreads();
    sum = reds[0] + reds[1] + reds[2] + reds[3];
    out[row * HIDc + t] = v - mx - logf(sum);
}

// ---------------- launch (two-stream fork-join, twice) ----------------
extern "C" void kernel_launch(void* const* d_in, const int* in_sizes, int n_in,
                              void* d_out, int out_size) {
    int i_x = 0, i_W1 = 4, i_b1 = 5, i_Wp = 6, i_bp = 7, i_ei = 8;
    for (int i = 0; i < n_in; i++) {
        int sz = in_sizes[i];
        if (sz == NNc * CINc)       i_x  = i;
        else if (sz == CINc * HIDc) i_W1 = i;
        else if (sz == HIDc)        i_b1 = i;
        else if (sz == HIDc * KCc)  i_Wp = i;
        else if (sz == KCc)         i_bp = i;
        else if (sz == 2 * EEc)     i_ei = i;
    }
    const float* x   = (const float*)d_in[i_x];
    const float* gnw = (const float*)d_in[1];
    const float* gnb = (const float*)d_in[2];
    const float* gms = (const float*)d_in[3];
    const float* W1  = (const float*)d_in[i_W1];
    const float* b1  = (const float*)d_in[i_b1];
    const float* Wp  = (const float*)d_in[i_Wp];
    const float* bp  = (const float*)d_in[i_bp];
    const void*  ei  = d_in[i_ei];

    float* out = (float*)d_out;
    float* out_loss = out + Bg*KCc*HIDc;          // 65536
    float* out_s    = out + Bg*KCc*HIDc + 1;      // 65537

    cudaStream_t s2;
    cudaEvent_t evFork, evJoin, evFin, evTail;
    cudaStreamCreateWithFlags(&s2, cudaStreamNonBlocking);
    cudaEventCreateWithFlags(&evFork, cudaEventDisableTiming);
    cudaEventCreateWithFlags(&evJoin, cudaEventDisableTiming);
    cudaEventCreateWithFlags(&evFin,  cudaEventDisableTiming);
    cudaEventCreateWithFlags(&evTail, cudaEventDisableTiming);

    // main stream: zero, then fork
    k_zero<<<1024, 256>>>();
    cudaEventRecord(evFork, 0);
    cudaStreamWaitEvent(s2, evFork, 0);

    // x chain on s2 (gn_part + gemm1 overlap the edge chain)
    k_gn_part<<<dim3(Bg, 16), 256, 0, s2>>>(x);
    k_gemm1<<<NNc/32, 256, 0, s2>>>(x, gnw, gnb, gms, W1);
    cudaEventRecord(evJoin, s2);

    // edge chain on main stream
    k_convert_deg<<<EEc/256, 256>>>(ei);
    k_scan<<<NNc/256, 256>>>();
    k_fill<<<EEc/256, 256>>>();

    // join: gather needs both chains
    cudaStreamWaitEvent(0, evJoin, 0);
    k_gather<<<NNc/8, 256>>>();
    k_fin_red<<<dim3(Bg, 64), 256>>>(b1, Wp, bp, out_s);

    // second fork: trace+losses (s2) overlap outx (main)
    cudaEventRecord(evFin, 0);
    cudaStreamWaitEvent(s2, evFin, 0);
    k_trace<<<NNc/8, 256, 0, s2>>>(out_s);
    k_losses<<<1, 512, 0, s2>>>(out_loss);
    cudaEventRecord(evTail, s2);

    k_outx<<<Bg*KCc, 128>>>(out);
    cudaStreamWaitEvent(0, evTail, 0);

    cudaEventDestroy(evFork);
    cudaEventDestroy(evJoin);
    cudaEventDestroy(evFin);
    cudaEventDestroy(evTail);
    cudaStreamDestroy(s2);
}

// round 16
// speedup vs baseline: 1.6250x; 1.0274x over previous
#include <cuda_runtime.h>

// Problem constants
#define Bg    16
#define NPGc  2048
#define NNc   32768      // Bg * NPGc
#define CINc  64
#define HIDc  128
#define KCc   32
#define EEc   524288

// ---------------- device scratch ----------------
__device__ float4 g_hlin4[NNc*HIDc/4];    // xn @ W1 (pre-aggregation)
#define g_hlin ((float*)g_hlin4)

__device__ int   g_src[EEc];
__device__ int   g_dst[EEc];
__device__ int   g_rank[EEc];             // rank of edge within its dst bucket
__device__ int   g_csrc[EEc];             // CSR column (src) indices, grouped by dst
__device__ int   g_degi[NNc];             // in-degree (int)
__device__ int   g_rowptr[NNc];           // CSR row starts
__device__ int   g_counter;               // scan base allocator

__device__ float g_gnsum[Bg*CINc];
__device__ float g_gnsq[Bg*CINc];
__device__ float g_dis[NNc];              // rsqrt(in_deg + 1)
__device__ float g_degsrc[NNc];           // DMoN degrees (out-degree)
__device__ float g_ecount[Bg];
__device__ float g_trace[Bg];             // sum_e dot(s_src, s_dst)
__device__ float g_sx[Bg*KCc*HIDc];       // S^T X per graph
__device__ float g_ss[Bg*KCc*KCc];        // S^T S per graph
__device__ float g_ca[Bg*KCc];            // S^T degrees
__device__ float g_cs[Bg*KCc];            // cluster sizes

// ---------------- f32x2 helpers ----------------
__device__ __forceinline__ unsigned long long f2pack(float x, float y) {
    unsigned long long r;
    asm("mov.b64 %0, {%1, %2};" : "=l"(r) : "f"(x), "f"(y));
    return r;
}
__device__ __forceinline__ unsigned long long ffma2(unsigned long long a,
                                                    unsigned long long b,
                                                    unsigned long long c) {
    unsigned long long d;
    asm("fma.rn.f32x2 %0, %1, %2, %3;" : "=l"(d) : "l"(a), "l"(b), "l"(c));
    return d;
}
__device__ __forceinline__ float2 f2unpack(unsigned long long v) {
    float2 f;
    asm("mov.b64 {%0, %1}, %2;" : "=f"(f.x), "=f"(f.y) : "l"(v));
    return f;
}

// ---------------- K0: zero small accumulators ----------------
__global__ __launch_bounds__(256) void k_zero() {
    int i0 = blockIdx.x * blockDim.x + threadIdx.x;
    int stride = gridDim.x * blockDim.x;
    for (int i = i0; i < NNc; i += stride) { g_degi[i] = 0; g_degsrc[i] = 0.f; }
    for (int i = i0; i < Bg*KCc*HIDc; i += stride) g_sx[i] = 0.f;
    for (int i = i0; i < Bg*KCc*KCc; i += stride) g_ss[i] = 0.f;
    for (int i = i0; i < Bg*KCc; i += stride) { g_ca[i] = 0.f; g_cs[i] = 0.f; }
    for (int i = i0; i < Bg*CINc; i += stride) { g_gnsum[i] = 0.f; g_gnsq[i] = 0.f; }
    if (i0 < Bg) { g_ecount[i0] = 0.f; g_trace[i0] = 0.f; }
    if (i0 == 0) g_counter = 0;
}

// ---------------- K1: edge convert + in-degree + in-bucket rank (ILP 2) ----------------
__global__ __launch_bounds__(256) void k_convert_deg(const void* __restrict__ ebuf) {
    __shared__ int nz;
    int t = threadIdx.x;
    if (t == 0) nz = 0;
    __syncthreads();
    int e0 = blockIdx.x * 256 + t;   // grid 1024 -> 2 edges/thread
    const int* w32 = (const int*)ebuf;
    unsigned any = __ballot_sync(0xffffffffu, w32[e0 * 2 + 1] != 0);
    if ((t & 31) == 0 && any) atomicOr(&nz, 1);
    __syncthreads();
    int is32 = nz;
#pragma unroll
    for (int u = 0; u < 2; u++) {
        int e = e0 + u * (EEc / 2);
        int s, d;
        if (is32 == 0) {   // int64
            const long long* p = (const long long*)ebuf;
            s = (int)p[e] & (NNc - 1);
            d = (int)p[EEc + e] & (NNc - 1);
        } else {           // int32
            s = w32[e] & (NNc - 1);
            d = w32[EEc + e] & (NNc - 1);
        }
        g_src[e] = s;
        g_dst[e] = d;
        g_rank[e] = atomicAdd(&g_degi[d], 1);
    }
}

// ---------------- K2: single-pass scan (atomic base) + dis ----------------
__global__ __launch_bounds__(256) void k_scan() {
    __shared__ int sm[256];
    __shared__ int base;
    int t = threadIdx.x;
    int n = blockIdx.x * 256 + t;
    int d = g_degi[n];
    sm[t] = d;
    __syncthreads();
    for (int o = 1; o < 256; o <<= 1) {
        int a = (t >= o) ? sm[t - o] : 0;
        __syncthreads();
        sm[t] += a;
        __syncthreads();
    }
    if (t == 255) base = atomicAdd(&g_counter, sm[255]);
    __syncthreads();
    g_rowptr[n] = base + sm[t] - d;
    g_dis[n] = rsqrtf((float)d + 1.f);
}

// ---------------- K3: atomic-free CSR fill + out-degree histogram ----------------
__global__ __launch_bounds__(256) void k_fill() {
    int e = blockIdx.x * 256 + threadIdx.x;   // grid 2048
    int d = g_dst[e];
    int s = g_src[e];
    g_csrc[g_rowptr[d] + g_rank[e]] = s;
    atomicAdd(&g_degsrc[s], 1.f);
}

// ---------------- K4: GraphNorm partial sums ----------------
__global__ __launch_bounds__(256) void k_gn_part(const float* __restrict__ x) {
    __shared__ float ssum[256], ssq[256];
    int b = blockIdx.x;
    int c = threadIdx.x & 63, r0 = threadIdx.x >> 6;
    const float* xb = x + (size_t)b * NPGc * CINc + (size_t)blockIdx.y * 128 * CINc;
    float s = 0.f, q = 0.f;
    for (int r = r0; r < 128; r += 4) {
        float v = xb[r * CINc + c];
        s += v; q += v * v;
    }
    ssum[threadIdx.x] = s; ssq[threadIdx.x] = q;
    __syncthreads();
    if (threadIdx.x < 64) {
        s = ssum[c] + ssum[c+64] + ssum[c+128] + ssum[c+192];
        q = ssq[c] + ssq[c+64] + ssq[c+128] + ssq[c+192];
        atomicAdd(&g_gnsum[b*CINc + c], s);
        atomicAdd(&g_gnsq[b*CINc + c], q);
    }
}

// ---------------- K5: GN finalize (per-block) + apply + GEMM (f32x2) ----------------
__global__ __launch_bounds__(256) void k_gemm1(const float* __restrict__ x,
                                               const float* __restrict__ gnw,
                                               const float* __restrict__ gnb,
                                               const float* __restrict__ gms,
                                               const float* __restrict__ W1) {
    __shared__ float Ws[CINc][HIDc];     // 32 KB
    __shared__ float Xs[32][CINc + 1];   // 8.1 KB
    __shared__ float sshift[CINc], sscale[CINc];
    int n0 = blockIdx.x * 32;
    int b = n0 / NPGc;
    if (threadIdx.x < CINc) {
        int c = threadIdx.x;
        float mean = g_gnsum[b*CINc + c] * (1.f / NPGc);
        float ms = gms[c];
        float var = g_gnsq[b*CINc + c] * (1.f / NPGc)
                  - 2.f * ms * mean * mean + ms * ms * mean * mean;
        sshift[c] = mean * ms;
        sscale[c] = gnw[c] * rsqrtf(var + 1e-5f);
    }
    for (int i = threadIdx.x; i < CINc * HIDc; i += 256)
        Ws[i >> 7][i & 127] = W1[i];
    __syncthreads();
    for (int i = threadIdx.x; i < 32 * CINc; i += 256) {
        int r = i >> 6, c = i & 63;
        float v = x[(size_t)(n0 + r) * CINc + c];
        Xs[r][c] = (v - sshift[c]) * sscale[c] + gnb[c];
    }
    __syncthreads();

    int q = threadIdx.x & 7;
    int jg = threadIdx.x >> 3;
    unsigned long long acc2[4][2];
#pragma unroll
    for (int i = 0; i < 4; i++) { acc2[i][0] = 0ull; acc2[i][1] = 0ull; }

    for (int k = 0; k < CINc; k++) {
        unsigned long long w01 = *(const unsigned long long*)&Ws[k][jg*4];
        unsigned long long w23 = *(const unsigned long long*)&Ws[k][jg*4+2];
#pragma unroll
        for (int i = 0; i < 4; i++) {
            float a = Xs[q*4+i][k];
            unsigned long long a2 = f2pack(a, a);
            acc2[i][0] = ffma2(a2, w01, acc2[i][0]);
            acc2[i][1] = ffma2(a2, w23, acc2[i][1]);
        }
    }
#pragma unroll
    for (int i = 0; i < 4; i++) {
        float2 f01 = f2unpack(acc2[i][0]);
        float2 f23 = f2unpack(acc2[i][1]);
        g_hlin4[(size_t)(n0 + q*4 + i) * (HIDc/4) + jg] =
            make_float4(f01.x, f01.y, f23.x, f23.y);
    }
}

// ---------------- K6: FUSED gather + finalize-h + softmax + node reductions ----------------
// grid (Bg, 64): 32 nodes per block. Phase A: each warp gathers 4 nodes'
// neighbor sums (shuffled index prefetch) + self-loop + bias + relu -> sH.
// Phase B: softmax + S^T H / S^T S / ca / cs reductions over 2 tiles of 16.
__global__ __launch_bounds__(256) void k_fin_red(const float* __restrict__ b1,
                                                 const float* __restrict__ Wp,
                                                 const float* __restrict__ bp,
                                                 float* __restrict__ out_s) {
    __shared__ float Wps[HIDc * KCc];  // 16 KB
    __shared__ float sH[32][HIDc];     // 16 KB
    __shared__ float sS[16][KCc];      // 2 KB
    __shared__ float sD[16];
    __shared__ float b1s[HIDc];
    __shared__ float bps[KCc];
    int tid = threadIdx.x;
    int b = blockIdx.x;
    int n0 = b * NPGc + blockIdx.y * 32;
    for (int i = tid; i < HIDc * KCc; i += 256) Wps[i] = Wp[i];
    if (tid < HIDc) b1s[tid] = b1[tid];
    if (tid < KCc)  bps[tid] = bp[tid];
    __syncthreads();

    int warp = tid >> 5, lane = tid & 31;

    // ---- Phase A: gather 4 nodes per warp ----
#pragma unroll
    for (int u = 0; u < 4; u++) {
        int nl = warp * 4 + u;
        int n = n0 + nl;
        int rs  = g_rowptr[n];
        int deg = g_degi[n];
        float disd = g_dis[n];
        unsigned long long a01 = 0ull, a23 = 0ull;
        for (int base = 0; base < deg; base += 32) {
            int l = base + lane;
            int idx = 0; float cl = 0.f;
            if (l < deg) {
                idx = g_csrc[rs + l];
                cl = disd * g_dis[idx];
            }
            int cnt = min(32, deg - base);
#pragma unroll 4
            for (int i = 0; i < cnt; i++) {
                int s  = __shfl_sync(0xffffffffu, idx, i);
                float c = __shfl_sync(0xffffffffu, cl, i);
                float4 v = g_hlin4[(size_t)s * (HIDc/4) + lane];
                unsigned long long c2 = f2pack(c, c);
                a01 = ffma2(c2, f2pack(v.x, v.y), a01);
                a23 = ffma2(c2, f2pack(v.z, v.w), a23);
            }
        }
        // self-loop + bias + relu
        float4 hv = g_hlin4[(size_t)n * (HIDc/4) + lane];
        float dd = disd * disd;
        float2 f01 = f2unpack(a01), f23 = f2unpack(a23);
        float4 r;
        r.x = fmaxf(f01.x + dd * hv.x + b1s[lane*4+0], 0.f);
        r.y = fmaxf(f01.y + dd * hv.y + b1s[lane*4+1], 0.f);
        r.z = fmaxf(f23.x + dd * hv.z + b1s[lane*4+2], 0.f);
        r.w = fmaxf(f23.y + dd * hv.w + b1s[lane*4+3], 0.f);
        *(float4*)&sH[nl][lane*4] = r;
    }
    __syncthreads();

    // ---- Phase B: softmax + reductions over 2 tiles of 16 nodes ----
    int k = tid >> 3, j8 = tid & 7;
    unsigned long long accx2[8];
#pragma unroll
    for (int i = 0; i < 8; i++) accx2[i] = 0ull;
    float accss[4] = {0.f, 0.f, 0.f, 0.f};
    float accca = 0.f, acccs = 0.f, eacc = 0.f;

    for (int tile = 0; tile < 2; tile++) {
        if (tile > 0) __syncthreads();   // protect sS reuse
        if (tid < 16) sD[tid] = g_degsrc[n0 + tile * 16 + tid];
#pragma unroll
        for (int u = 0; u < 2; u++) {
            int nl = warp * 2 + u;            // 0..15 within tile
            int gl = tile * 16 + nl;          // 0..31 within block
            float acc = bps[lane];
#pragma unroll 8
            for (int j = 0; j < HIDc; j++)
                acc += sH[gl][j] * Wps[j * KCc + lane];
            float m = acc;
#pragma unroll
            for (int o = 16; o; o >>= 1) m = fmaxf(m, __shfl_xor_sync(0xffffffffu, m, o));
            float e = expf(acc - m);
            float sum = e;
#pragma unroll
            for (int o = 16; o; o >>= 1) sum += __shfl_xor_sync(0xffffffffu, sum, o);
            float sv = e / sum;
            sS[nl][lane] = sv;
            out_s[(size_t)(n0 + gl) * KCc + lane] = sv;
        }
        __syncthreads();
        if (tid < 16) eacc += sD[tid];
#pragma unroll 4
        for (int nn = 0; nn < 16; nn++) {
            float sk = sS[nn][k];
            unsigned long long sk2 = f2pack(sk, sk);
            const unsigned long long* row = (const unsigned long long*)&sH[tile*16 + nn][0];
#pragma unroll
            for (int jj = 0; jj < 8; jj++)
                accx2[jj] = ffma2(sk2, row[j8 + jj * 8], accx2[jj]);
#pragma unroll
            for (int i = 0; i < 4; i++) {
                int idx = tid * 4 + i;
                accss[i] += sS[nn][idx >> 5] * sS[nn][idx & 31];
            }
            if (tid < 32) {
                float sv = sS[nn][tid];
                accca += sv * sD[nn];
                acccs += sv;
            }
        }
    }
#pragma unroll
    for (int jj = 0; jj < 8; jj++) {
        float2 r = f2unpack(accx2[jj]);
        atomicAdd(&g_sx[b*KCc*HIDc + k*HIDc + 2*j8 + 16*jj], r.x);
        atomicAdd(&g_sx[b*KCc*HIDc + k*HIDc + 2*j8 + 16*jj + 1], r.y);
    }
#pragma unroll
    for (int i = 0; i < 4; i++)
        atomicAdd(&g_ss[b*KCc*KCc + tid*4 + i], accss[i]);
    if (tid < 32) {
        atomicAdd(&g_ca[b*KCc + tid], accca);
        atomicAdd(&g_cs[b*KCc + tid], acccs);
    }
    if (tid < 16) atomicAdd(&g_ecount[b], eacc);
}

// ---------------- K8: spectral trace via CSR ----------------
__global__ __launch_bounds__(256) void k_trace(const float* __restrict__ s) {
    __shared__ float sacc;
    if (threadIdx.x == 0) sacc = 0.f;
    __syncthreads();
    int n = (blockIdx.x * 256 + threadIdx.x) >> 5;   // global warp id = node id
    int lane = threadIdx.x & 31;
    int rs  = g_rowptr[n];
    int deg = g_degi[n];
    float accv = 0.f;
    for (int base = 0; base < deg; base += 32) {
        int l = base + lane;
        int idx = (l < deg) ? g_csrc[rs + l] : 0;
        int cnt = min(32, deg - base);
#pragma unroll 4
        for (int i = 0; i < cnt; i++) {
            int sn = __shfl_sync(0xffffffffu, idx, i);
            accv += s[(size_t)sn * KCc + lane];
        }
    }
    float p = accv * s[(size_t)n * KCc + lane];
#pragma unroll
    for (int o = 16; o; o >>= 1) p += __shfl_xor_sync(0xffffffffu, p, o);
    if (lane == 0) atomicAdd(&sacc, p);
    __syncthreads();
    if (threadIdx.x == 0) atomicAdd(&g_trace[(blockIdx.x * 8) >> 11], sacc);
}

// ---------------- K9: losses ----------------
__global__ __launch_bounds__(512) void k_losses(float* __restrict__ out_loss) {
    __shared__ float bl[Bg];
    int w = threadIdx.x >> 5, lane = threadIdx.x & 31;
    if (w < Bg) {
        int b = w;
        float m = g_ecount[b] * 0.5f;
        float q = 0.f;
        for (int i = 0; i < 32; i++) {
            float v = g_ss[b*1024 + i*32 + lane];
            q += v * v;
        }
#pragma unroll
        for (int o = 16; o; o >>= 1) q += __shfl_xor_sync(0xffffffffu, q, o);
        float nrm = sqrtf(q);
        float inv_sk = rsqrtf((float)KCc);
        float oo = 0.f;
        for (int i = 0; i < 32; i++) {
            float v = g_ss[b*1024 + i*32 + lane] / nrm - ((i == lane) ? inv_sk : 0.f);
            oo += v * v;
        }
#pragma unroll
        for (int o = 16; o; o >>= 1) oo += __shfl_xor_sync(0xffffffffu, oo, o);
        float cav = g_ca[b*KCc + lane];
        float ca2 = cav * cav;
#pragma unroll
        for (int o = 16; o; o >>= 1) ca2 += __shfl_xor_sync(0xffffffffu, ca2, o);
        float csv = g_cs[b*KCc + lane];
        float cs2 = csv * csv;
#pragma unroll
        for (int o = 16; o; o >>= 1) cs2 += __shfl_xor_sync(0xffffffffu, cs2, o);
        if (lane == 0) {
            float spec = -(g_trace[b] - ca2 / (2.f * m)) / (2.f * m);
            float ortho = sqrtf(oo);
            float clus = sqrtf(cs2) / (float)NPGc * sqrtf((float)KCc) - 1.f;
            bl[b] = spec + ortho + clus;
        }
    }
    __syncthreads();
    if (threadIdx.x == 0) {
        float t = 0.f;
        for (int i = 0; i < Bg; i++) t += bl[i];
        out_loss[0] = t / (float)Bg;
    }
}

// ---------------- K10: selu + log_softmax of out_x ----------------
__global__ __launch_bounds__(128) void k_outx(float* __restrict__ out) {
    __shared__ float redm[4], reds[4];
    int row = blockIdx.x;
    int t = threadIdx.x;
    int warp = t >> 5, lane = t & 31;
    float v = g_sx[row * HIDc + t];
    const float sc = 1.0507009873554805f, al = 1.6732632423543772f;
    v = (v > 0.f) ? sc * v : sc * al * (expf(v) - 1.f);
    float mx = v;
#pragma unroll
    for (int o = 16; o; o >>= 1) mx = fmaxf(mx, __shfl_xor_sync(0xffffffffu, mx, o));
    if (lane == 0) redm[warp] = mx;
    __syncthreads();
    mx = fmaxf(fmaxf(redm[0], redm[1]), fmaxf(redm[2], redm[3]));
    float e = expf(v - mx);
    float sum = e;
#pragma unroll
    for (int o = 16; o; o >>= 1) sum += __shfl_xor_sync(0xffffffffu, sum, o);
    if (lane == 0) reds[warp] = sum;
    __syncthreads();
    sum = reds[0] + reds[1] + reds[2] + reds[3];
    out[row * HIDc + t] = v - mx - logf(sum);
}

// ---------------- launch (two-stream fork-join, twice) ----------------
extern "C" void kernel_launch(void* const* d_in, const int* in_sizes, int n_in,
                              void* d_out, int out_size) {
    int i_x = 0, i_W1 = 4, i_b1 = 5, i_Wp = 6, i_bp = 7, i_ei = 8;
    for (int i = 0; i < n_in; i++) {
        int sz = in_sizes[i];
        if (sz == NNc * CINc)       i_x  = i;
        else if (sz == CINc * HIDc) i_W1 = i;
        else if (sz == HIDc)        i_b1 = i;
        else if (sz == HIDc * KCc)  i_Wp = i;
        else if (sz == KCc)         i_bp = i;
        else if (sz == 2 * EEc)     i_ei = i;
    }
    const float* x   = (const float*)d_in[i_x];
    const float* gnw = (const float*)d_in[1];
    const float* gnb = (const float*)d_in[2];
    const float* gms = (const float*)d_in[3];
    const float* W1  = (const float*)d_in[i_W1];
    const float* b1  = (const float*)d_in[i_b1];
    const float* Wp  = (const float*)d_in[i_Wp];
    const float* bp  = (const float*)d_in[i_bp];
    const void*  ei  = d_in[i_ei];

    float* out = (float*)d_out;
    float* out_loss = out + Bg*KCc*HIDc;          // 65536
    float* out_s    = out + Bg*KCc*HIDc + 1;      // 65537

    cudaStream_t s2;
    cudaEvent_t evFork, evJoin, evFin, evTail;
    cudaStreamCreateWithFlags(&s2, cudaStreamNonBlocking);
    cudaEventCreateWithFlags(&evFork, cudaEventDisableTiming);
    cudaEventCreateWithFlags(&evJoin, cudaEventDisableTiming);
    cudaEventCreateWithFlags(&evFin,  cudaEventDisableTiming);
    cudaEventCreateWithFlags(&evTail, cudaEventDisableTiming);

    // main stream: zero, then fork
    k_zero<<<1024, 256>>>();
    cudaEventRecord(evFork, 0);
    cudaStreamWaitEvent(s2, evFork, 0);

    // x chain on s2 (gn_part + gemm1 overlap the edge chain)
    k_gn_part<<<dim3(Bg, 16), 256, 0, s2>>>(x);
    k_gemm1<<<NNc/32, 256, 0, s2>>>(x, gnw, gnb, gms, W1);
    cudaEventRecord(evJoin, s2);

    // edge chain on main stream
    k_convert_deg<<<1024, 256>>>(ei);
    k_scan<<<NNc/256, 256>>>();
    k_fill<<<EEc/256, 256>>>();

    // join: fused fin_red needs both chains
    cudaStreamWaitEvent(0, evJoin, 0);
    k_fin_red<<<dim3(Bg, 64), 256>>>(b1, Wp, bp, out_s);

    // second fork: trace+losses (s2) overlap outx (main)
    cudaEventRecord(evFin, 0);
    cudaStreamWaitEvent(s2, evFin, 0);
    k_trace<<<NNc/8, 256, 0, s2>>>(out_s);
    k_losses<<<1, 512, 0, s2>>>(out_loss);
    cudaEventRecord(evTail, s2);

    k_outx<<<Bg*KCc, 128>>>(out);
    cudaStreamWaitEvent(0, evTail, 0);

    cudaEventDestroy(evFork);
    cudaEventDestroy(evJoin);
    cudaEventDestroy(evFin);
    cudaEventDestroy(evTail);
    cudaStreamDestroy(s2);
}